// round 1
// baseline (speedup 1.0000x reference)
#include <cuda_runtime.h>
#include <math.h>

#define N_NODES 50000
#define N_EDGES 800000
#define F_IN    512
#define HID     256
#define NCLS    40
#define WDIM    50

// ------------------------- scratch (device globals) -------------------------
__device__ float g_h   [(size_t)N_NODES * HID];   // h1 = x@W1+b1
__device__ float g_e   [(size_t)N_EDGES * HID];   // exp(ow) per edge (reused layer2 as [E,40])
__device__ float g_sum [(size_t)N_NODES * HID];   // per-source softmax denominators (reused layer2)
__device__ float g_out1[(size_t)N_NODES * HID];   // layer-1 aggregated output
__device__ float g_h2  [(size_t)N_NODES * NCLS];  // h2 = elu(out1)@W2+b2

// ------------------------------- utilities ---------------------------------
__global__ void zero_k(float* __restrict__ p, int n) {
    int i = blockIdx.x * blockDim.x + threadIdx.x;
    if (i < n) p[i] = 0.0f;
}

// ----------------------- node GEMM: out = act(A)@W + b ----------------------
// A: [M,K] row-major, W: [K,C] row-major. Block tile: TE rows x C cols.
// Thread micro-tile: VE rows x 4 cols. act_in=1 applies ELU to A while staging.
template<int C, int K, int CT, int RT, int VE>
__global__ void node_gemm(const float* __restrict__ A, const float* __restrict__ W,
                          const float* __restrict__ bias, float* __restrict__ out,
                          int M, int act_in)
{
    constexpr int TE = RT * VE;
    constexpr int KS = K + 4;        // pad keeps 16B alignment, breaks bank conflicts
    constexpr int NT = CT * RT;
    __shared__ float As[TE * KS];

    const int tid = threadIdx.x;
    const int ct = tid % CT, rt = tid / CT;
    const int c0 = ct * 4, r0 = rt * VE;
    const int rBase = blockIdx.x * TE;

    for (int idx = tid; idx < TE * (K / 4); idx += NT) {
        int row = idx / (K / 4);
        int kc  = (idx % (K / 4)) * 4;
        int gr  = rBase + row;
        float4 v = make_float4(0.f, 0.f, 0.f, 0.f);
        if (gr < M) v = *(const float4*)&A[(size_t)gr * K + kc];
        if (act_in) {  // ELU
            v.x = v.x > 0.f ? v.x : expm1f(v.x);
            v.y = v.y > 0.f ? v.y : expm1f(v.y);
            v.z = v.z > 0.f ? v.z : expm1f(v.z);
            v.w = v.w > 0.f ? v.w : expm1f(v.w);
        }
        *(float4*)&As[row * KS + kc] = v;
    }
    __syncthreads();

    float acc[VE][4];
    #pragma unroll
    for (int i = 0; i < VE; i++) { acc[i][0]=0.f; acc[i][1]=0.f; acc[i][2]=0.f; acc[i][3]=0.f; }

    #pragma unroll 4
    for (int k = 0; k < K; k++) {
        float4 w = *(const float4*)&W[k * C + c0];
        #pragma unroll
        for (int i = 0; i < VE; i++) {
            float a = As[(r0 + i) * KS + k];
            acc[i][0] += a * w.x; acc[i][1] += a * w.y;
            acc[i][2] += a * w.z; acc[i][3] += a * w.w;
        }
    }

    float4 b = *(const float4*)&bias[c0];
    #pragma unroll
    for (int i = 0; i < VE; i++) {
        int gr = rBase + r0 + i;
        if (gr < M) {
            float4 o = make_float4(acc[i][0]+b.x, acc[i][1]+b.y, acc[i][2]+b.z, acc[i][3]+b.w);
            *(float4*)&out[(size_t)gr * C + c0] = o;
        }
    }
}

// ---- fused edge MLP: e = exp(prelu(w_mul@w0, a)@w1 + b1), segsum[src] += e --
// w0: [WDIM,C], w1: [C,C]. Block tile: TE edges x C cols, t tile lives in SMEM.
template<int C, int CT, int RT, int VE>
__global__ void edge_mlp(const float* __restrict__ wmul, const int* __restrict__ src,
                         const float* __restrict__ w0,   const float* __restrict__ pa,
                         const float* __restrict__ w1,   const float* __restrict__ b1,
                         float* __restrict__ eout, float* __restrict__ segsum)
{
    constexpr int TE = RT * VE;
    constexpr int NT = CT * RT;
    __shared__ float smw[TE * WDIM];   // w_mul tile
    __shared__ float st [TE * C];      // t = prelu(w_mul @ w0)

    const int tid = threadIdx.x;
    const int ct = tid % CT, rt = tid / CT;
    const int c0 = ct * 4;
    const int e0 = rt * VE;
    const int eBase = blockIdx.x * TE;

    for (int idx = tid; idx < TE * WDIM; idx += NT)
        smw[idx] = wmul[(size_t)eBase * WDIM + idx];
    __syncthreads();

    // ---- stage 1: t = prelu(w_mul @ w0) ----
    float acc[VE][4];
    #pragma unroll
    for (int i = 0; i < VE; i++) { acc[i][0]=0.f; acc[i][1]=0.f; acc[i][2]=0.f; acc[i][3]=0.f; }

    #pragma unroll 2
    for (int k = 0; k < WDIM; k++) {
        float4 w = *(const float4*)&w0[k * C + c0];
        #pragma unroll
        for (int i = 0; i < VE; i++) {
            float a = smw[(e0 + i) * WDIM + k];
            acc[i][0] += a * w.x; acc[i][1] += a * w.y;
            acc[i][2] += a * w.z; acc[i][3] += a * w.w;
        }
    }
    {
        float4 al = *(const float4*)&pa[c0];
        #pragma unroll
        for (int i = 0; i < VE; i++) {
            float4 t;
            t.x = acc[i][0] >= 0.f ? acc[i][0] : al.x * acc[i][0];
            t.y = acc[i][1] >= 0.f ? acc[i][1] : al.y * acc[i][1];
            t.z = acc[i][2] >= 0.f ? acc[i][2] : al.z * acc[i][2];
            t.w = acc[i][3] >= 0.f ? acc[i][3] : al.w * acc[i][3];
            *(float4*)&st[(e0 + i) * C + c0] = t;
        }
    }
    __syncthreads();

    // ---- stage 2: ow = t @ w1 + b1; e = exp(ow); segsum[src] += e ----
    #pragma unroll
    for (int i = 0; i < VE; i++) { acc[i][0]=0.f; acc[i][1]=0.f; acc[i][2]=0.f; acc[i][3]=0.f; }

    #pragma unroll 4
    for (int k = 0; k < C; k++) {
        float4 w = *(const float4*)&w1[k * C + c0];
        #pragma unroll
        for (int i = 0; i < VE; i++) {
            float a = st[(e0 + i) * C + k];
            acc[i][0] += a * w.x; acc[i][1] += a * w.y;
            acc[i][2] += a * w.z; acc[i][3] += a * w.w;
        }
    }

    float4 bb = *(const float4*)&b1[c0];
    #pragma unroll
    for (int i = 0; i < VE; i++) {
        int edge = eBase + e0 + i;
        float4 ev;
        ev.x = __expf(acc[i][0] + bb.x);
        ev.y = __expf(acc[i][1] + bb.y);
        ev.z = __expf(acc[i][2] + bb.z);
        ev.w = __expf(acc[i][3] + bb.w);
        *(float4*)&eout[(size_t)edge * C + c0] = ev;
        int s = src[edge];
        float* sp = &segsum[(size_t)s * C + c0];
        atomicAdd(sp + 0, ev.x);
        atomicAdd(sp + 1, ev.y);
        atomicAdd(sp + 2, ev.z);
        atomicAdd(sp + 3, ev.w);
    }
}

// -------- message + scatter: out[dst] += (e/segsum[src]) * h[src] ----------
__global__ void msg256(const float* __restrict__ ew, const int* __restrict__ src,
                       const int* __restrict__ dst, const float* __restrict__ segsum,
                       const float* __restrict__ h, float* __restrict__ out)
{
    int tid  = threadIdx.x;
    int eloc = tid >> 6;
    int c0   = (tid & 63) * 4;
    int edge = blockIdx.x * 4 + eloc;
    int s = src[edge], d = dst[edge];
    float4 ev = *(const float4*)&ew    [(size_t)edge * HID + c0];
    float4 sv = *(const float4*)&segsum[(size_t)s    * HID + c0];
    float4 hv = *(const float4*)&h     [(size_t)s    * HID + c0];
    float* op = &out[(size_t)d * HID + c0];
    atomicAdd(op + 0, ev.x / sv.x * hv.x);
    atomicAdd(op + 1, ev.y / sv.y * hv.y);
    atomicAdd(op + 2, ev.z / sv.z * hv.z);
    atomicAdd(op + 3, ev.w / sv.w * hv.w);
}

__global__ void msg40(const float* __restrict__ ew, const int* __restrict__ src,
                      const int* __restrict__ dst, const float* __restrict__ segsum,
                      const float* __restrict__ h, float* __restrict__ out)
{
    int tid  = threadIdx.x;          // 320 threads: 32 edges x 10 col-groups
    int eloc = tid / 10;
    int c0   = (tid % 10) * 4;
    int edge = blockIdx.x * 32 + eloc;
    int s = src[edge], d = dst[edge];
    float4 ev = *(const float4*)&ew    [(size_t)edge * NCLS + c0];
    float4 sv = *(const float4*)&segsum[(size_t)s    * NCLS + c0];
    float4 hv = *(const float4*)&h     [(size_t)s    * NCLS + c0];
    float* op = &out[(size_t)d * NCLS + c0];
    atomicAdd(op + 0, ev.x / sv.x * hv.x);
    atomicAdd(op + 1, ev.y / sv.y * hv.y);
    atomicAdd(op + 2, ev.z / sv.z * hv.z);
    atomicAdd(op + 3, ev.w / sv.w * hv.w);
}

// --------------------------- in-place log_softmax ---------------------------
__global__ void logsoftmax40(float* __restrict__ out, int M)
{
    int warp = (blockIdx.x * blockDim.x + threadIdx.x) >> 5;
    int lane = threadIdx.x & 31;
    if (warp >= M) return;
    float* row = out + (size_t)warp * NCLS;
    float v0 = row[lane];
    float v1 = (lane < 8) ? row[32 + lane] : -INFINITY;
    float m = fmaxf(v0, v1);
    #pragma unroll
    for (int o = 16; o; o >>= 1) m = fmaxf(m, __shfl_xor_sync(0xffffffffu, m, o));
    float s = expf(v0 - m) + ((lane < 8) ? expf(v1 - m) : 0.f);
    #pragma unroll
    for (int o = 16; o; o >>= 1) s += __shfl_xor_sync(0xffffffffu, s, o);
    float l = m + logf(s);
    row[lane] = v0 - l;
    if (lane < 8) row[32 + lane] = v1 - l;
}

// --------------------------------- launch -----------------------------------
extern "C" void kernel_launch(void* const* d_in, const int* in_sizes, int n_in,
                              void* d_out, int out_size)
{
    const float* x    = (const float*)d_in[0];
    const int*   ei   = (const int*)  d_in[1];
    const float* wmul = (const float*)d_in[2];
    const float* W1   = (const float*)d_in[3];
    const float* b1   = (const float*)d_in[4];
    const float* m1w0 = (const float*)d_in[5];
    const float* m1a  = (const float*)d_in[6];
    const float* m1w1 = (const float*)d_in[7];
    const float* m1b1 = (const float*)d_in[8];
    const float* W2   = (const float*)d_in[9];
    const float* b2   = (const float*)d_in[10];
    const float* m2w0 = (const float*)d_in[11];
    const float* m2a  = (const float*)d_in[12];
    const float* m2w1 = (const float*)d_in[13];
    const float* m2b1 = (const float*)d_in[14];
    float* out = (float*)d_out;

    const int* src = ei;            // edge_index[0]
    const int* dst = ei + N_EDGES;  // edge_index[1]

    float *p_h, *p_e, *p_sum, *p_out1, *p_h2;
    cudaGetSymbolAddress((void**)&p_h,    g_h);
    cudaGetSymbolAddress((void**)&p_e,    g_e);
    cudaGetSymbolAddress((void**)&p_sum,  g_sum);
    cudaGetSymbolAddress((void**)&p_out1, g_out1);
    cudaGetSymbolAddress((void**)&p_h2,   g_h2);

    // ---------------- layer 1 (C = 256) ----------------
    const int n1 = N_NODES * HID;
    zero_k<<<(n1 + 255) / 256, 256>>>(p_sum,  n1);
    zero_k<<<(n1 + 255) / 256, 256>>>(p_out1, n1);

    // h1 = x @ W1 + b1   [50000,512]x[512,256]
    node_gemm<HID, F_IN, 64, 4, 4><<<N_NODES / 16, 256>>>(x, W1, b1, p_h, N_NODES, 0);

    // e = exp(prelu(wmul@w0,a)@w1 + b1), segsum[src] += e
    edge_mlp<HID, 64, 4, 4><<<N_EDGES / 16, 256>>>(wmul, src, m1w0, m1a, m1w1, m1b1, p_e, p_sum);

    // out1[dst] += (e/segsum[src]) * h1[src]
    msg256<<<N_EDGES / 4, 256>>>(p_e, src, dst, p_sum, p_h, p_out1);

    // ---------------- layer 2 (C = 40) ----------------
    const int n2 = N_NODES * NCLS;
    zero_k<<<(n2 + 255) / 256, 256>>>(p_sum, n2);
    zero_k<<<(n2 + 255) / 256, 256>>>(out,   n2);

    // h2 = elu(out1) @ W2 + b2   [50000,256]x[256,40], ELU fused into staging
    node_gemm<NCLS, HID, 10, 16, 2><<<(N_NODES + 31) / 32, 160>>>(p_out1, W2, b2, p_h2, N_NODES, 1);

    edge_mlp<NCLS, 10, 16, 4><<<N_EDGES / 64, 160>>>(wmul, src, m2w0, m2a, m2w1, m2b1, p_e, p_sum);

    msg40<<<N_EDGES / 32, 320>>>(p_e, src, dst, p_sum, p_h2, out);

    logsoftmax40<<<(N_NODES + 7) / 8, 256>>>(out, N_NODES);
}

// round 4
// speedup vs baseline: 1.4892x; 1.4892x over previous
#include <cuda_runtime.h>
#include <cuda_fp16.h>
#include <stdint.h>
#include <math.h>

#define N_NODES 50000
#define N_EDGES 800000
#define F_IN    512
#define HID     256
#define NCLS    40
#define WDIM    50

// ------------------------- scratch (device globals) -------------------------
__device__ float  g_h   [(size_t)N_NODES * HID];   // h1 = x@W1+b1 (then /= segsum)
__device__ float  g_e   [(size_t)N_EDGES * HID];   // exp(ow) per edge (reused layer2 [E,40])
__device__ float  g_sum [(size_t)N_NODES * HID];   // per-source softmax denominators
__device__ float  g_out1[(size_t)N_NODES * HID];   // layer-1 aggregated output
__device__ float  g_h2  [(size_t)N_NODES * NCLS];  // h2 = elu(out1)@W2+b2 (then /= segsum)
__device__ __half g_w1h [(size_t)HID * HID];       // w1 transposed, fp16: [n][k]

// ------------------------------- utilities ---------------------------------
__global__ void zero_k(float* __restrict__ p, int n) {
    int i = blockIdx.x * blockDim.x + threadIdx.x;
    if (i < n) p[i] = 0.0f;
}

__global__ void div_k(float* __restrict__ h, const float* __restrict__ s, int n) {
    int i = blockIdx.x * blockDim.x + threadIdx.x;
    if (i < n) h[i] = h[i] / s[i];
}

// transpose+convert w1 [k][n] f32 -> w1h [n][k] fp16
__global__ void conv_w1(const float* __restrict__ w1, __half* __restrict__ w1h) {
    int i = blockIdx.x * 256 + threadIdx.x;     // i over 256*256
    int n = i >> 8, k = i & 255;
    w1h[n * HID + k] = __float2half(w1[k * HID + n]);
}

// ----------------------- node GEMM: out = act(A)@W + b ----------------------
template<int C, int K, int CT, int RT, int VE>
__global__ void node_gemm(const float* __restrict__ A, const float* __restrict__ W,
                          const float* __restrict__ bias, float* __restrict__ out,
                          int M, int act_in)
{
    constexpr int TE = RT * VE;
    constexpr int KS = K + 4;
    constexpr int NT = CT * RT;
    __shared__ float As[TE * KS];

    const int tid = threadIdx.x;
    const int ct = tid % CT, rt = tid / CT;
    const int c0 = ct * 4, r0 = rt * VE;
    const int rBase = blockIdx.x * TE;

    for (int idx = tid; idx < TE * (K / 4); idx += NT) {
        int row = idx / (K / 4);
        int kc  = (idx % (K / 4)) * 4;
        int gr  = rBase + row;
        float4 v = make_float4(0.f, 0.f, 0.f, 0.f);
        if (gr < M) v = *(const float4*)&A[(size_t)gr * K + kc];
        if (act_in) {  // ELU
            v.x = v.x > 0.f ? v.x : expm1f(v.x);
            v.y = v.y > 0.f ? v.y : expm1f(v.y);
            v.z = v.z > 0.f ? v.z : expm1f(v.z);
            v.w = v.w > 0.f ? v.w : expm1f(v.w);
        }
        *(float4*)&As[row * KS + kc] = v;
    }
    __syncthreads();

    float acc[VE][4];
    #pragma unroll
    for (int i = 0; i < VE; i++) { acc[i][0]=0.f; acc[i][1]=0.f; acc[i][2]=0.f; acc[i][3]=0.f; }

    #pragma unroll 4
    for (int k = 0; k < K; k++) {
        float4 w = *(const float4*)&W[k * C + c0];
        #pragma unroll
        for (int i = 0; i < VE; i++) {
            float a = As[(r0 + i) * KS + k];
            acc[i][0] += a * w.x; acc[i][1] += a * w.y;
            acc[i][2] += a * w.z; acc[i][3] += a * w.w;
        }
    }

    float4 b = *(const float4*)&bias[c0];
    #pragma unroll
    for (int i = 0; i < VE; i++) {
        int gr = rBase + r0 + i;
        if (gr < M) {
            float4 o = make_float4(acc[i][0]+b.x, acc[i][1]+b.y, acc[i][2]+b.z, acc[i][3]+b.w);
            *(float4*)&out[(size_t)gr * C + c0] = o;
        }
    }
}

// ============== layer-1 edge MLP with fp16 tensor-core stage 2 ==============
// Block: 256 threads (8 warps), processes 8 tiles of 64 edges (512 edges).
// smem: sB = w1^T fp16 [256][264] (loaded once), tA = t fp16 [64][264],
//       smw = wmul f32 [64][52].
// Stage1 (fp32 FFMA): t = prelu(wmul @ w0); stage2 (HMMA): ow = t @ w1.
#define TC_TILES   8
#define TC_TE      64
#define TC_BSTRIDE 264          // 256 + 8 half pad -> conflict-free LDS
#define TC_SMEM    ((HID*TC_BSTRIDE + TC_TE*TC_BSTRIDE) * 2 + TC_TE*52*4)

__device__ __forceinline__ void mma16816(float c[4], const unsigned int a[4],
                                         unsigned int b0, unsigned int b1) {
    asm volatile(
        "mma.sync.aligned.m16n8k16.row.col.f32.f16.f16.f32 "
        "{%0,%1,%2,%3}, {%4,%5,%6,%7}, {%8,%9}, {%0,%1,%2,%3};\n"
        : "+f"(c[0]), "+f"(c[1]), "+f"(c[2]), "+f"(c[3])
        : "r"(a[0]), "r"(a[1]), "r"(a[2]), "r"(a[3]), "r"(b0), "r"(b1));
}

__global__ void __launch_bounds__(256, 1)
edge_mlp_tc(const float* __restrict__ wmul, const int* __restrict__ src,
            const float* __restrict__ w0,   const float* __restrict__ pa,
            const __half* __restrict__ w1h, const float* __restrict__ b1,
            float* __restrict__ eout, float* __restrict__ segsum)
{
    extern __shared__ char smraw[];
    __half* sB  = (__half*)smraw;                      // [256][264]
    __half* tA  = sB + HID * TC_BSTRIDE;               // [64][264]
    float*  smw = (float*)(tA + TC_TE * TC_BSTRIDE);   // [64][52]

    const int tid  = threadIdx.x;
    const int lane = tid & 31, warp = tid >> 5;
    const int g = lane >> 2, t2 = (lane & 3) * 2;
    const int rowbase = (warp >> 2) * 32;              // 0 or 32
    const int colbase = (warp & 3) * 64;               // 0/64/128/192

    // load w1^T fp16 into smem once (uint4 = 8 halfs)
    for (int idx = tid; idx < HID * (HID / 8); idx += 256) {
        int n = idx >> 5, kc = (idx & 31) * 8;
        *(uint4*)&sB[n * TC_BSTRIDE + kc] = *(const uint4*)&w1h[n * HID + kc];
    }

    // stage1 thread mapping: 64 cols-of-4 x 4 row-groups, 16 rows each
    const int ct = tid % 64, rt = tid / 64;
    const int c0 = ct * 4,  r0 = rt * 16;

    for (int tile = 0; tile < TC_TILES; tile++) {
        int eBase = blockIdx.x * (TC_TILES * TC_TE) + tile * TC_TE;
        if (eBase >= N_EDGES) break;   // uniform per block

        // ---- load wmul tile ----
        for (int idx = tid; idx < TC_TE * WDIM; idx += 256) {
            int row = idx / WDIM, k = idx % WDIM;
            smw[row * 52 + k] = wmul[(size_t)(eBase + row) * WDIM + k];
        }
        __syncthreads();

        // ---- stage 1 (fp32): t = prelu(wmul @ w0) -> tA fp16 ----
        {
            float acc[16][4];
            #pragma unroll
            for (int i = 0; i < 16; i++) { acc[i][0]=0.f; acc[i][1]=0.f; acc[i][2]=0.f; acc[i][3]=0.f; }
            #pragma unroll 2
            for (int k = 0; k < WDIM; k++) {
                float4 w = *(const float4*)&w0[k * HID + c0];
                #pragma unroll
                for (int i = 0; i < 16; i++) {
                    float a = smw[(r0 + i) * 52 + k];
                    acc[i][0] += a * w.x; acc[i][1] += a * w.y;
                    acc[i][2] += a * w.z; acc[i][3] += a * w.w;
                }
            }
            float4 al = *(const float4*)&pa[c0];
            #pragma unroll
            for (int i = 0; i < 16; i++) {
                float tx = acc[i][0] >= 0.f ? acc[i][0] : al.x * acc[i][0];
                float ty = acc[i][1] >= 0.f ? acc[i][1] : al.y * acc[i][1];
                float tz = acc[i][2] >= 0.f ? acc[i][2] : al.z * acc[i][2];
                float tw = acc[i][3] >= 0.f ? acc[i][3] : al.w * acc[i][3];
                __half2* dp = (__half2*)&tA[(r0 + i) * TC_BSTRIDE + c0];
                dp[0] = __floats2half2_rn(tx, ty);
                dp[1] = __floats2half2_rn(tz, tw);
            }
        }
        __syncthreads();

        // ---- stage 2 (fp16 HMMA): ow = t @ w1 ----
        float c[2][8][4];
        #pragma unroll
        for (int mt = 0; mt < 2; mt++)
            #pragma unroll
            for (int nt = 0; nt < 8; nt++)
                { c[mt][nt][0]=0.f; c[mt][nt][1]=0.f; c[mt][nt][2]=0.f; c[mt][nt][3]=0.f; }

        #pragma unroll
        for (int ks = 0; ks < 16; ks++) {
            unsigned int a[2][4];
            #pragma unroll
            for (int mt = 0; mt < 2; mt++) {
                const __half* ap = &tA[(rowbase + mt * 16 + g) * TC_BSTRIDE + ks * 16 + t2];
                a[mt][0] = *(const unsigned int*)ap;
                a[mt][1] = *(const unsigned int*)(ap + 8 * TC_BSTRIDE);
                a[mt][2] = *(const unsigned int*)(ap + 8);
                a[mt][3] = *(const unsigned int*)(ap + 8 * TC_BSTRIDE + 8);
            }
            #pragma unroll
            for (int nt = 0; nt < 8; nt++) {
                const __half* bp = &sB[(colbase + nt * 8 + g) * TC_BSTRIDE + ks * 16 + t2];
                unsigned int b0  = *(const unsigned int*)bp;
                unsigned int b1r = *(const unsigned int*)(bp + 8);
                mma16816(c[0][nt], a[0], b0, b1r);
                mma16816(c[1][nt], a[1], b0, b1r);
            }
        }

        // ---- epilogue: e = exp(ow + b1); store; segsum[src] += e ----
        #pragma unroll
        for (int mt = 0; mt < 2; mt++) {
            int r  = rowbase + mt * 16 + g;
            int e0 = eBase + r, e1 = e0 + 8;
            int s0 = src[e0],  s1 = src[e1];
            #pragma unroll
            for (int nt = 0; nt < 8; nt++) {
                int col = colbase + nt * 8 + t2;
                float2 bb = *(const float2*)&b1[col];
                float v0 = __expf(c[mt][nt][0] + bb.x);
                float v1 = __expf(c[mt][nt][1] + bb.y);
                float v2 = __expf(c[mt][nt][2] + bb.x);
                float v3 = __expf(c[mt][nt][3] + bb.y);
                *(float2*)&eout[(size_t)e0 * HID + col] = make_float2(v0, v1);
                *(float2*)&eout[(size_t)e1 * HID + col] = make_float2(v2, v3);
                float* p0 = &segsum[(size_t)s0 * HID + col];
                float* p1 = &segsum[(size_t)s1 * HID + col];
                atomicAdd(p0,     v0);
                atomicAdd(p0 + 1, v1);
                atomicAdd(p1,     v2);
                atomicAdd(p1 + 1, v3);
            }
        }
        __syncthreads();   // protect smw/tA before next tile
    }
}

// ------------- layer-2 edge MLP (C=40, fp32, as before) --------------------
template<int C, int CT, int RT, int VE>
__global__ void edge_mlp(const float* __restrict__ wmul, const int* __restrict__ src,
                         const float* __restrict__ w0,   const float* __restrict__ pa,
                         const float* __restrict__ w1,   const float* __restrict__ b1,
                         float* __restrict__ eout, float* __restrict__ segsum)
{
    constexpr int TE = RT * VE;
    constexpr int NT = CT * RT;
    __shared__ float smw[TE * WDIM];
    __shared__ float st [TE * C];

    const int tid = threadIdx.x;
    const int ct = tid % CT, rt = tid / CT;
    const int c0 = ct * 4;
    const int e0 = rt * VE;
    const int eBase = blockIdx.x * TE;

    for (int idx = tid; idx < TE * WDIM; idx += NT)
        smw[idx] = wmul[(size_t)eBase * WDIM + idx];
    __syncthreads();

    float acc[VE][4];
    #pragma unroll
    for (int i = 0; i < VE; i++) { acc[i][0]=0.f; acc[i][1]=0.f; acc[i][2]=0.f; acc[i][3]=0.f; }

    #pragma unroll 2
    for (int k = 0; k < WDIM; k++) {
        float4 w = *(const float4*)&w0[k * C + c0];
        #pragma unroll
        for (int i = 0; i < VE; i++) {
            float a = smw[(e0 + i) * WDIM + k];
            acc[i][0] += a * w.x; acc[i][1] += a * w.y;
            acc[i][2] += a * w.z; acc[i][3] += a * w.w;
        }
    }
    {
        float4 al = *(const float4*)&pa[c0];
        #pragma unroll
        for (int i = 0; i < VE; i++) {
            float4 t;
            t.x = acc[i][0] >= 0.f ? acc[i][0] : al.x * acc[i][0];
            t.y = acc[i][1] >= 0.f ? acc[i][1] : al.y * acc[i][1];
            t.z = acc[i][2] >= 0.f ? acc[i][2] : al.z * acc[i][2];
            t.w = acc[i][3] >= 0.f ? acc[i][3] : al.w * acc[i][3];
            *(float4*)&st[(e0 + i) * C + c0] = t;
        }
    }
    __syncthreads();

    #pragma unroll
    for (int i = 0; i < VE; i++) { acc[i][0]=0.f; acc[i][1]=0.f; acc[i][2]=0.f; acc[i][3]=0.f; }

    #pragma unroll 4
    for (int k = 0; k < C; k++) {
        float4 w = *(const float4*)&w1[k * C + c0];
        #pragma unroll
        for (int i = 0; i < VE; i++) {
            float a = st[(e0 + i) * C + k];
            acc[i][0] += a * w.x; acc[i][1] += a * w.y;
            acc[i][2] += a * w.z; acc[i][3] += a * w.w;
        }
    }

    float4 bb = *(const float4*)&b1[c0];
    #pragma unroll
    for (int i = 0; i < VE; i++) {
        int edge = eBase + e0 + i;
        float4 ev;
        ev.x = __expf(acc[i][0] + bb.x);
        ev.y = __expf(acc[i][1] + bb.y);
        ev.z = __expf(acc[i][2] + bb.z);
        ev.w = __expf(acc[i][3] + bb.w);
        *(float4*)&eout[(size_t)edge * C + c0] = ev;
        int s = src[edge];
        float* sp = &segsum[(size_t)s * C + c0];
        atomicAdd(sp + 0, ev.x);
        atomicAdd(sp + 1, ev.y);
        atomicAdd(sp + 2, ev.z);
        atomicAdd(sp + 3, ev.w);
    }
}

// ---------- message + scatter: out[dst] += e * hn[src]  (hn = h/segsum) ----
__global__ void msg256(const float* __restrict__ ew, const int* __restrict__ src,
                       const int* __restrict__ dst, const float* __restrict__ hn,
                       float* __restrict__ out)
{
    int tid  = threadIdx.x;
    int eloc = tid >> 6;
    int c0   = (tid & 63) * 4;
    int edge = blockIdx.x * 4 + eloc;
    int s = src[edge], d = dst[edge];
    float4 ev = *(const float4*)&ew[(size_t)edge * HID + c0];
    float4 hv = *(const float4*)&hn[(size_t)s    * HID + c0];
    float* op = &out[(size_t)d * HID + c0];
    atomicAdd(op + 0, ev.x * hv.x);
    atomicAdd(op + 1, ev.y * hv.y);
    atomicAdd(op + 2, ev.z * hv.z);
    atomicAdd(op + 3, ev.w * hv.w);
}

__global__ void msg40(const float* __restrict__ ew, const int* __restrict__ src,
                      const int* __restrict__ dst, const float* __restrict__ hn,
                      float* __restrict__ out)
{
    int tid  = threadIdx.x;          // 320 threads: 32 edges x 10 col-groups
    int eloc = tid / 10;
    int c0   = (tid % 10) * 4;
    int edge = blockIdx.x * 32 + eloc;
    int s = src[edge], d = dst[edge];
    float4 ev = *(const float4*)&ew[(size_t)edge * NCLS + c0];
    float4 hv = *(const float4*)&hn[(size_t)s    * NCLS + c0];
    float* op = &out[(size_t)d * NCLS + c0];
    atomicAdd(op + 0, ev.x * hv.x);
    atomicAdd(op + 1, ev.y * hv.y);
    atomicAdd(op + 2, ev.z * hv.z);
    atomicAdd(op + 3, ev.w * hv.w);
}

// --------------------------- in-place log_softmax ---------------------------
__global__ void logsoftmax40(float* __restrict__ out, int M)
{
    int warp = (blockIdx.x * blockDim.x + threadIdx.x) >> 5;
    int lane = threadIdx.x & 31;
    if (warp >= M) return;
    float* row = out + (size_t)warp * NCLS;
    float v0 = row[lane];
    float v1 = (lane < 8) ? row[32 + lane] : -INFINITY;
    float m = fmaxf(v0, v1);
    #pragma unroll
    for (int o = 16; o; o >>= 1) m = fmaxf(m, __shfl_xor_sync(0xffffffffu, m, o));
    float s = expf(v0 - m) + ((lane < 8) ? expf(v1 - m) : 0.f);
    #pragma unroll
    for (int o = 16; o; o >>= 1) s += __shfl_xor_sync(0xffffffffu, s, o);
    float l = m + logf(s);
    row[lane] = v0 - l;
    if (lane < 8) row[32 + lane] = v1 - l;
}

// --------------------------------- launch -----------------------------------
extern "C" void kernel_launch(void* const* d_in, const int* in_sizes, int n_in,
                              void* d_out, int out_size)
{
    const float* x    = (const float*)d_in[0];
    const int*   ei   = (const int*)  d_in[1];
    const float* wmul = (const float*)d_in[2];
    const float* W1   = (const float*)d_in[3];
    const float* b1   = (const float*)d_in[4];
    const float* m1w0 = (const float*)d_in[5];
    const float* m1a  = (const float*)d_in[6];
    const float* m1w1 = (const float*)d_in[7];
    const float* m1b1 = (const float*)d_in[8];
    const float* W2   = (const float*)d_in[9];
    const float* b2   = (const float*)d_in[10];
    const float* m2w0 = (const float*)d_in[11];
    const float* m2a  = (const float*)d_in[12];
    const float* m2w1 = (const float*)d_in[13];
    const float* m2b1 = (const float*)d_in[14];
    float* out = (float*)d_out;

    const int* src = ei;            // edge_index[0]
    const int* dst = ei + N_EDGES;  // edge_index[1]

    float *p_h, *p_e, *p_sum, *p_out1, *p_h2;
    __half* p_w1h;
    cudaGetSymbolAddress((void**)&p_h,    g_h);
    cudaGetSymbolAddress((void**)&p_e,    g_e);
    cudaGetSymbolAddress((void**)&p_sum,  g_sum);
    cudaGetSymbolAddress((void**)&p_out1, g_out1);
    cudaGetSymbolAddress((void**)&p_h2,   g_h2);
    cudaGetSymbolAddress((void**)&p_w1h,  g_w1h);

    cudaFuncSetAttribute(edge_mlp_tc, cudaFuncAttributeMaxDynamicSharedMemorySize, TC_SMEM);

    // ---------------- layer 1 (C = 256) ----------------
    const int n1 = N_NODES * HID;
    zero_k<<<(n1 + 255) / 256, 256>>>(p_sum,  n1);
    zero_k<<<(n1 + 255) / 256, 256>>>(p_out1, n1);
    conv_w1<<<HID * HID / 256, 256>>>(m1w1, p_w1h);

    // h1 = x @ W1 + b1
    node_gemm<HID, F_IN, 64, 4, 4><<<N_NODES / 16, 256>>>(x, W1, b1, p_h, N_NODES, 0);

    // e = exp(prelu(wmul@w0,a)@w1 + b1), segsum[src] += e  (tensor-core stage 2)
    {
        int grid = (N_EDGES + TC_TILES * TC_TE - 1) / (TC_TILES * TC_TE);
        edge_mlp_tc<<<grid, 256, TC_SMEM>>>(wmul, src, m1w0, m1a, p_w1h, m1b1, p_e, p_sum);
    }

    // hn = h1 / segsum (in place)
    div_k<<<(n1 + 255) / 256, 256>>>(p_h, p_sum, n1);

    // out1[dst] += e * hn[src]
    msg256<<<N_EDGES / 4, 256>>>(p_e, src, dst, p_h, p_out1);

    // ---------------- layer 2 (C = 40) ----------------
    const int n2 = N_NODES * NCLS;
    zero_k<<<(n2 + 255) / 256, 256>>>(p_sum, n2);
    zero_k<<<(n2 + 255) / 256, 256>>>(out,   n2);

    // h2 = elu(out1) @ W2 + b2
    node_gemm<NCLS, HID, 10, 16, 2><<<(N_NODES + 31) / 32, 160>>>(p_out1, W2, b2, p_h2, N_NODES, 1);

    edge_mlp<NCLS, 10, 16, 4><<<N_EDGES / 64, 160>>>(wmul, src, m2w0, m2a, m2w1, m2b1, p_e, p_sum);

    // hn2 = h2 / segsum (in place)
    div_k<<<(n2 + 255) / 256, 256>>>(p_h2, p_sum, n2);

    msg40<<<N_EDGES / 32, 320>>>(p_e, src, dst, p_h2, out);

    logsoftmax40<<<(N_NODES + 7) / 8, 256>>>(out, N_NODES);
}

// round 5
// speedup vs baseline: 2.1899x; 1.4705x over previous
#include <cuda_runtime.h>
#include <cuda_fp16.h>
#include <stdint.h>
#include <math.h>

#define N_NODES 50000
#define N_EDGES 800000
#define F_IN    512
#define HID     256
#define NCLS    40
#define WDIM    50

// ------------------------- scratch (device globals) -------------------------
__device__ float  g_h   [(size_t)N_NODES * HID];    // h1 (then /= segsum)
__device__ float  g_e   [(size_t)N_EDGES * NCLS];   // layer-2 exp(ow) [E,40] f32
__device__ __half g_eh  [(size_t)N_EDGES * HID];    // layer-1 exp(ow) [E,256] fp16
__device__ float  g_sum [(size_t)N_NODES * HID];    // softmax denominators
__device__ float  g_out1[(size_t)N_NODES * HID];    // layer-1 aggregated output
__device__ float  g_h2  [(size_t)N_NODES * NCLS];   // h2 (then /= segsum)
__device__ __half g_w1h [(size_t)HID * HID];        // m1_w1^T fp16 [n][k]
__device__ __half g_w0h [(size_t)HID * 64];         // m1_w0^T fp16 [n][k pad 64]
__device__ __half g_xh  [(size_t)N_NODES * F_IN];   // x fp16
__device__ __half g_W1t [(size_t)HID * F_IN];       // W1^T fp16 [n][k]

// ------------------------------- utilities ---------------------------------
__global__ void zero_k(float* __restrict__ p, int n) {
    int i = blockIdx.x * blockDim.x + threadIdx.x;
    if (i < n) p[i] = 0.0f;
}

__global__ void div_k(float* __restrict__ h, const float* __restrict__ s, int n) {
    int i = blockIdx.x * blockDim.x + threadIdx.x;
    if (i < n) h[i] = h[i] / s[i];
}

// x f32 -> fp16 (4-wide)
__global__ void conv_x(const float* __restrict__ x, __half* __restrict__ xh, int n4) {
    int i = blockIdx.x * blockDim.x + threadIdx.x;
    if (i < n4) {
        float4 v = *(const float4*)&x[i * 4];
        __half2* d = (__half2*)&xh[i * 4];
        d[0] = __floats2half2_rn(v.x, v.y);
        d[1] = __floats2half2_rn(v.z, v.w);
    }
}

// transpose+convert w [k][n] f32 -> wt fp16 [n][kpad], zero pad k>=K
template<int K, int N, int KP>
__global__ void conv_wt(const float* __restrict__ w, __half* __restrict__ wt) {
    int i = blockIdx.x * 256 + threadIdx.x;          // over N*KP
    if (i >= N * KP) return;
    int n = i / KP, k = i % KP;
    wt[i] = (k < K) ? __float2half(w[k * N + n]) : __half(0.0f);
}

// ------------------------------ mma helper ----------------------------------
__device__ __forceinline__ void mma16816(float c[4], const unsigned int a[4],
                                         unsigned int b0, unsigned int b1) {
    asm volatile(
        "mma.sync.aligned.m16n8k16.row.col.f32.f16.f16.f32 "
        "{%0,%1,%2,%3}, {%4,%5,%6,%7}, {%8,%9}, {%0,%1,%2,%3};\n"
        : "+f"(c[0]), "+f"(c[1]), "+f"(c[2]), "+f"(c[3])
        : "r"(a[0]), "r"(a[1]), "r"(a[2]), "r"(a[3]), "r"(b0), "r"(b1));
}

// ================= tensor-core node GEMM: out = A@B^T + bias =================
// A: [M][K] fp16 row-major, Bt: [N][K] fp16. BM=128, BN=64, BK=64.
// 256 threads = 8 warps (2 m-groups x 4 n-groups); warp tile 64x16.
template<int K, int N>
__global__ void __launch_bounds__(256)
node_gemm_tc(const __half* __restrict__ A, const __half* __restrict__ Bt,
             const float* __restrict__ bias, float* __restrict__ out, int M)
{
    constexpr int BM = 128, BN = 64, BK = 64, KS = 72;
    __shared__ __half As[BM * KS];
    __shared__ __half Bs[BN * KS];

    const int tid = threadIdx.x;
    const int lane = tid & 31, warp = tid >> 5;
    const int g = lane >> 2, t2 = (lane & 3) * 2;
    const int wm = warp >> 2, wn = warp & 3;         // m-group(0-1), n-group(0-3)
    const int rBase = blockIdx.x * BM;
    const int cBase = blockIdx.y * BN;

    float c[4][2][4];
    #pragma unroll
    for (int mt = 0; mt < 4; mt++)
        #pragma unroll
        for (int nt = 0; nt < 2; nt++)
            { c[mt][nt][0]=0.f; c[mt][nt][1]=0.f; c[mt][nt][2]=0.f; c[mt][nt][3]=0.f; }

    for (int k0 = 0; k0 < K; k0 += BK) {
        // load A tile: 128x64 halfs = 1024 uint4, 4 per thread
        #pragma unroll
        for (int i = 0; i < 4; i++) {
            int idx = tid + i * 256;
            int row = idx >> 3, seg = idx & 7;
            int gr = rBase + row;
            uint4 v = make_uint4(0u, 0u, 0u, 0u);
            if (gr < M) v = *(const uint4*)&A[(size_t)gr * K + k0 + seg * 8];
            *(uint4*)&As[row * KS + seg * 8] = v;
        }
        // load B tile: 64x64 halfs = 512 uint4, 2 per thread
        #pragma unroll
        for (int i = 0; i < 2; i++) {
            int idx = tid + i * 256;
            int n = idx >> 3, seg = idx & 7;
            *(uint4*)&Bs[n * KS + seg * 8] =
                *(const uint4*)&Bt[(size_t)(cBase + n) * K + k0 + seg * 8];
        }
        __syncthreads();

        #pragma unroll
        for (int ks = 0; ks < 4; ks++) {
            unsigned int a[4][4];
            #pragma unroll
            for (int mt = 0; mt < 4; mt++) {
                const __half* ap = &As[(wm * 64 + mt * 16 + g) * KS + ks * 16 + t2];
                a[mt][0] = *(const unsigned int*)ap;
                a[mt][1] = *(const unsigned int*)(ap + 8 * KS);
                a[mt][2] = *(const unsigned int*)(ap + 8);
                a[mt][3] = *(const unsigned int*)(ap + 8 * KS + 8);
            }
            #pragma unroll
            for (int nt = 0; nt < 2; nt++) {
                const __half* bp = &Bs[(wn * 16 + nt * 8 + g) * KS + ks * 16 + t2];
                unsigned int b0  = *(const unsigned int*)bp;
                unsigned int b1r = *(const unsigned int*)(bp + 8);
                #pragma unroll
                for (int mt = 0; mt < 4; mt++)
                    mma16816(c[mt][nt], a[mt], b0, b1r);
            }
        }
        __syncthreads();
    }

    #pragma unroll
    for (int mt = 0; mt < 4; mt++) {
        int r0 = rBase + wm * 64 + mt * 16 + g;
        #pragma unroll
        for (int nt = 0; nt < 2; nt++) {
            int col = cBase + wn * 16 + nt * 8 + t2;
            float2 bb = *(const float2*)&bias[col];
            if (r0 < M)
                *(float2*)&out[(size_t)r0 * N + col] =
                    make_float2(c[mt][nt][0] + bb.x, c[mt][nt][1] + bb.y);
            if (r0 + 8 < M)
                *(float2*)&out[(size_t)(r0 + 8) * N + col] =
                    make_float2(c[mt][nt][2] + bb.x, c[mt][nt][3] + bb.y);
        }
    }
}

// ========== layer-1 edge MLP: both stages on fp16 tensor cores ==============
// Block: 256 threads (8 warps), 8 tiles of 64 edges.
// smem: sB = w1^T [256][264], sB0 = w0^T [256][72], tA [64][264], smwh [64][72]
#define TC_TILES   8
#define TC_TE      64
#define TC_BSTRIDE 264
#define TC_KP      64
#define TC_SMEM    ((HID*TC_BSTRIDE + HID*72 + TC_TE*TC_BSTRIDE + TC_TE*72) * 2)

__global__ void __launch_bounds__(256, 1)
edge_mlp_tc(const float* __restrict__ wmul, const int* __restrict__ src,
            const __half* __restrict__ w0h, const float* __restrict__ pa,
            const __half* __restrict__ w1h, const float* __restrict__ b1,
            __half* __restrict__ eout, float* __restrict__ segsum)
{
    extern __shared__ char smraw[];
    __half* sB   = (__half*)smraw;                    // [256][264] w1^T
    __half* sB0  = sB  + HID * TC_BSTRIDE;            // [256][72]  w0^T
    __half* tA   = sB0 + HID * 72;                    // [64][264]  t fp16
    __half* smwh = tA  + TC_TE * TC_BSTRIDE;          // [64][72]   wmul fp16

    const int tid  = threadIdx.x;
    const int lane = tid & 31, warp = tid >> 5;
    const int g = lane >> 2, t2 = (lane & 3) * 2;
    const int rowbase = (warp >> 2) * 32;             // 0 or 32
    const int colbase = (warp & 3) * 64;              // 0/64/128/192

    // load w1^T and w0^T into smem once
    for (int idx = tid; idx < HID * (HID / 8); idx += 256) {
        int n = idx >> 5, kc = (idx & 31) * 8;
        *(uint4*)&sB[n * TC_BSTRIDE + kc] = *(const uint4*)&w1h[n * HID + kc];
    }
    for (int idx = tid; idx < HID * (TC_KP / 8); idx += 256) {
        int n = idx >> 3, kc = (idx & 7) * 8;
        *(uint4*)&sB0[n * 72 + kc] = *(const uint4*)&w0h[n * TC_KP + kc];
    }

    for (int tile = 0; tile < TC_TILES; tile++) {
        int eBase = blockIdx.x * (TC_TILES * TC_TE) + tile * TC_TE;
        if (eBase >= N_EDGES) break;

        // ---- load wmul tile -> fp16, zero-pad k to 64 ----
        for (int idx = tid; idx < TC_TE * 72; idx += 256) {
            int row = idx / 72, k = idx % 72;
            smwh[idx] = (k < WDIM)
                ? __float2half(wmul[(size_t)(eBase + row) * WDIM + k])
                : __half(0.0f);
        }
        __syncthreads();

        // ---- stage 1 (HMMA): t = prelu(wmul @ w0) -> tA fp16 ----
        {
            float c1[2][8][4];
            #pragma unroll
            for (int mt = 0; mt < 2; mt++)
                #pragma unroll
                for (int nt = 0; nt < 8; nt++)
                    { c1[mt][nt][0]=0.f; c1[mt][nt][1]=0.f; c1[mt][nt][2]=0.f; c1[mt][nt][3]=0.f; }

            #pragma unroll
            for (int ks = 0; ks < 4; ks++) {
                unsigned int a[2][4];
                #pragma unroll
                for (int mt = 0; mt < 2; mt++) {
                    const __half* ap = &smwh[(rowbase + mt * 16 + g) * 72 + ks * 16 + t2];
                    a[mt][0] = *(const unsigned int*)ap;
                    a[mt][1] = *(const unsigned int*)(ap + 8 * 72);
                    a[mt][2] = *(const unsigned int*)(ap + 8);
                    a[mt][3] = *(const unsigned int*)(ap + 8 * 72 + 8);
                }
                #pragma unroll
                for (int nt = 0; nt < 8; nt++) {
                    const __half* bp = &sB0[(colbase + nt * 8 + g) * 72 + ks * 16 + t2];
                    unsigned int b0  = *(const unsigned int*)bp;
                    unsigned int b1r = *(const unsigned int*)(bp + 8);
                    mma16816(c1[0][nt], a[0], b0, b1r);
                    mma16816(c1[1][nt], a[1], b0, b1r);
                }
            }

            #pragma unroll
            for (int mt = 0; mt < 2; mt++) {
                int r = rowbase + mt * 16 + g;
                #pragma unroll
                for (int nt = 0; nt < 8; nt++) {
                    int col = colbase + nt * 8 + t2;
                    float2 al = *(const float2*)&pa[col];
                    float v0 = c1[mt][nt][0] >= 0.f ? c1[mt][nt][0] : al.x * c1[mt][nt][0];
                    float v1 = c1[mt][nt][1] >= 0.f ? c1[mt][nt][1] : al.y * c1[mt][nt][1];
                    float v2 = c1[mt][nt][2] >= 0.f ? c1[mt][nt][2] : al.x * c1[mt][nt][2];
                    float v3 = c1[mt][nt][3] >= 0.f ? c1[mt][nt][3] : al.y * c1[mt][nt][3];
                    *(__half2*)&tA[r * TC_BSTRIDE + col]       = __floats2half2_rn(v0, v1);
                    *(__half2*)&tA[(r + 8) * TC_BSTRIDE + col] = __floats2half2_rn(v2, v3);
                }
            }
        }
        __syncthreads();

        // ---- stage 2 (HMMA): ow = t @ w1 ----
        float c[2][8][4];
        #pragma unroll
        for (int mt = 0; mt < 2; mt++)
            #pragma unroll
            for (int nt = 0; nt < 8; nt++)
                { c[mt][nt][0]=0.f; c[mt][nt][1]=0.f; c[mt][nt][2]=0.f; c[mt][nt][3]=0.f; }

        #pragma unroll
        for (int ks = 0; ks < 16; ks++) {
            unsigned int a[2][4];
            #pragma unroll
            for (int mt = 0; mt < 2; mt++) {
                const __half* ap = &tA[(rowbase + mt * 16 + g) * TC_BSTRIDE + ks * 16 + t2];
                a[mt][0] = *(const unsigned int*)ap;
                a[mt][1] = *(const unsigned int*)(ap + 8 * TC_BSTRIDE);
                a[mt][2] = *(const unsigned int*)(ap + 8);
                a[mt][3] = *(const unsigned int*)(ap + 8 * TC_BSTRIDE + 8);
            }
            #pragma unroll
            for (int nt = 0; nt < 8; nt++) {
                const __half* bp = &sB[(colbase + nt * 8 + g) * TC_BSTRIDE + ks * 16 + t2];
                unsigned int b0  = *(const unsigned int*)bp;
                unsigned int b1r = *(const unsigned int*)(bp + 8);
                mma16816(c[0][nt], a[0], b0, b1r);
                mma16816(c[1][nt], a[1], b0, b1r);
            }
        }

        // ---- epilogue: e = exp(ow + b1) -> fp16 store; segsum[src] += e ----
        #pragma unroll
        for (int mt = 0; mt < 2; mt++) {
            int r  = rowbase + mt * 16 + g;
            int e0 = eBase + r, e1 = e0 + 8;
            int s0 = src[e0],  s1 = src[e1];
            #pragma unroll
            for (int nt = 0; nt < 8; nt++) {
                int col = colbase + nt * 8 + t2;
                float2 bb = *(const float2*)&b1[col];
                float v0 = __expf(c[mt][nt][0] + bb.x);
                float v1 = __expf(c[mt][nt][1] + bb.y);
                float v2 = __expf(c[mt][nt][2] + bb.x);
                float v3 = __expf(c[mt][nt][3] + bb.y);
                *(__half2*)&eout[(size_t)e0 * HID + col] = __floats2half2_rn(v0, v1);
                *(__half2*)&eout[(size_t)e1 * HID + col] = __floats2half2_rn(v2, v3);
                float* p0 = &segsum[(size_t)s0 * HID + col];
                float* p1 = &segsum[(size_t)s1 * HID + col];
                atomicAdd(p0,     v0);
                atomicAdd(p0 + 1, v1);
                atomicAdd(p1,     v2);
                atomicAdd(p1 + 1, v3);
            }
        }
        __syncthreads();
    }
}

// ------------- layer-2 edge MLP (C=40, fp32) --------------------------------
template<int C, int CT, int RT, int VE>
__global__ void edge_mlp(const float* __restrict__ wmul, const int* __restrict__ src,
                         const float* __restrict__ w0,   const float* __restrict__ pa,
                         const float* __restrict__ w1,   const float* __restrict__ b1,
                         float* __restrict__ eout, float* __restrict__ segsum)
{
    constexpr int TE = RT * VE;
    constexpr int NT = CT * RT;
    __shared__ float smw[TE * WDIM];
    __shared__ float st [TE * C];

    const int tid = threadIdx.x;
    const int ct = tid % CT, rt = tid / CT;
    const int c0 = ct * 4;
    const int e0 = rt * VE;
    const int eBase = blockIdx.x * TE;

    for (int idx = tid; idx < TE * WDIM; idx += NT)
        smw[idx] = wmul[(size_t)eBase * WDIM + idx];
    __syncthreads();

    float acc[VE][4];
    #pragma unroll
    for (int i = 0; i < VE; i++) { acc[i][0]=0.f; acc[i][1]=0.f; acc[i][2]=0.f; acc[i][3]=0.f; }

    #pragma unroll 2
    for (int k = 0; k < WDIM; k++) {
        float4 w = *(const float4*)&w0[k * C + c0];
        #pragma unroll
        for (int i = 0; i < VE; i++) {
            float a = smw[(e0 + i) * WDIM + k];
            acc[i][0] += a * w.x; acc[i][1] += a * w.y;
            acc[i][2] += a * w.z; acc[i][3] += a * w.w;
        }
    }
    {
        float4 al = *(const float4*)&pa[c0];
        #pragma unroll
        for (int i = 0; i < VE; i++) {
            float4 t;
            t.x = acc[i][0] >= 0.f ? acc[i][0] : al.x * acc[i][0];
            t.y = acc[i][1] >= 0.f ? acc[i][1] : al.y * acc[i][1];
            t.z = acc[i][2] >= 0.f ? acc[i][2] : al.z * acc[i][2];
            t.w = acc[i][3] >= 0.f ? acc[i][3] : al.w * acc[i][3];
            *(float4*)&st[(e0 + i) * C + c0] = t;
        }
    }
    __syncthreads();

    #pragma unroll
    for (int i = 0; i < VE; i++) { acc[i][0]=0.f; acc[i][1]=0.f; acc[i][2]=0.f; acc[i][3]=0.f; }

    #pragma unroll 4
    for (int k = 0; k < C; k++) {
        float4 w = *(const float4*)&w1[k * C + c0];
        #pragma unroll
        for (int i = 0; i < VE; i++) {
            float a = st[(e0 + i) * C + k];
            acc[i][0] += a * w.x; acc[i][1] += a * w.y;
            acc[i][2] += a * w.z; acc[i][3] += a * w.w;
        }
    }

    float4 bb = *(const float4*)&b1[c0];
    #pragma unroll
    for (int i = 0; i < VE; i++) {
        int edge = eBase + e0 + i;
        float4 ev;
        ev.x = __expf(acc[i][0] + bb.x);
        ev.y = __expf(acc[i][1] + bb.y);
        ev.z = __expf(acc[i][2] + bb.z);
        ev.w = __expf(acc[i][3] + bb.w);
        *(float4*)&eout[(size_t)edge * C + c0] = ev;
        int s = src[edge];
        float* sp = &segsum[(size_t)s * C + c0];
        atomicAdd(sp + 0, ev.x);
        atomicAdd(sp + 1, ev.y);
        atomicAdd(sp + 2, ev.z);
        atomicAdd(sp + 3, ev.w);
    }
}

// ---------- message + scatter: out[dst] += e * hn[src]  (hn = h/segsum) ----
__global__ void msg256(const __half* __restrict__ ewh, const int* __restrict__ src,
                       const int* __restrict__ dst, const float* __restrict__ hn,
                       float* __restrict__ out)
{
    int tid  = threadIdx.x;
    int eloc = tid >> 6;
    int c0   = (tid & 63) * 4;
    int edge = blockIdx.x * 4 + eloc;
    int s = src[edge], d = dst[edge];
    const __half2* ep = (const __half2*)&ewh[(size_t)edge * HID + c0];
    float2 e01 = __half22float2(ep[0]);
    float2 e23 = __half22float2(ep[1]);
    float4 hv = *(const float4*)&hn[(size_t)s * HID + c0];
    float* op = &out[(size_t)d * HID + c0];
    atomicAdd(op + 0, e01.x * hv.x);
    atomicAdd(op + 1, e01.y * hv.y);
    atomicAdd(op + 2, e23.x * hv.z);
    atomicAdd(op + 3, e23.y * hv.w);
}

__global__ void msg40(const float* __restrict__ ew, const int* __restrict__ src,
                      const int* __restrict__ dst, const float* __restrict__ hn,
                      float* __restrict__ out)
{
    int tid  = threadIdx.x;          // 320 threads: 32 edges x 10 col-groups
    int eloc = tid / 10;
    int c0   = (tid % 10) * 4;
    int edge = blockIdx.x * 32 + eloc;
    int s = src[edge], d = dst[edge];
    float4 ev = *(const float4*)&ew[(size_t)edge * NCLS + c0];
    float4 hv = *(const float4*)&hn[(size_t)s    * NCLS + c0];
    float* op = &out[(size_t)d * NCLS + c0];
    atomicAdd(op + 0, ev.x * hv.x);
    atomicAdd(op + 1, ev.y * hv.y);
    atomicAdd(op + 2, ev.z * hv.z);
    atomicAdd(op + 3, ev.w * hv.w);
}

// ------------ node GEMM fp32 (layer-2, ELU fused into staging) ---------------
template<int C, int K, int CT, int RT, int VE>
__global__ void node_gemm(const float* __restrict__ A, const float* __restrict__ W,
                          const float* __restrict__ bias, float* __restrict__ out,
                          int M, int act_in)
{
    constexpr int TE = RT * VE;
    constexpr int KS = K + 4;
    constexpr int NT = CT * RT;
    __shared__ float As[TE * KS];

    const int tid = threadIdx.x;
    const int ct = tid % CT, rt = tid / CT;
    const int c0 = ct * 4, r0 = rt * VE;
    const int rBase = blockIdx.x * TE;

    for (int idx = tid; idx < TE * (K / 4); idx += NT) {
        int row = idx / (K / 4);
        int kc  = (idx % (K / 4)) * 4;
        int gr  = rBase + row;
        float4 v = make_float4(0.f, 0.f, 0.f, 0.f);
        if (gr < M) v = *(const float4*)&A[(size_t)gr * K + kc];
        if (act_in) {
            v.x = v.x > 0.f ? v.x : expm1f(v.x);
            v.y = v.y > 0.f ? v.y : expm1f(v.y);
            v.z = v.z > 0.f ? v.z : expm1f(v.z);
            v.w = v.w > 0.f ? v.w : expm1f(v.w);
        }
        *(float4*)&As[row * KS + kc] = v;
    }
    __syncthreads();

    float acc[VE][4];
    #pragma unroll
    for (int i = 0; i < VE; i++) { acc[i][0]=0.f; acc[i][1]=0.f; acc[i][2]=0.f; acc[i][3]=0.f; }

    #pragma unroll 4
    for (int k = 0; k < K; k++) {
        float4 w = *(const float4*)&W[k * C + c0];
        #pragma unroll
        for (int i = 0; i < VE; i++) {
            float a = As[(r0 + i) * KS + k];
            acc[i][0] += a * w.x; acc[i][1] += a * w.y;
            acc[i][2] += a * w.z; acc[i][3] += a * w.w;
        }
    }

    float4 b = *(const float4*)&bias[c0];
    #pragma unroll
    for (int i = 0; i < VE; i++) {
        int gr = rBase + r0 + i;
        if (gr < M) {
            float4 o = make_float4(acc[i][0]+b.x, acc[i][1]+b.y, acc[i][2]+b.z, acc[i][3]+b.w);
            *(float4*)&out[(size_t)gr * C + c0] = o;
        }
    }
}

// --------------------------- in-place log_softmax ---------------------------
__global__ void logsoftmax40(float* __restrict__ out, int M)
{
    int warp = (blockIdx.x * blockDim.x + threadIdx.x) >> 5;
    int lane = threadIdx.x & 31;
    if (warp >= M) return;
    float* row = out + (size_t)warp * NCLS;
    float v0 = row[lane];
    float v1 = (lane < 8) ? row[32 + lane] : -INFINITY;
    float m = fmaxf(v0, v1);
    #pragma unroll
    for (int o = 16; o; o >>= 1) m = fmaxf(m, __shfl_xor_sync(0xffffffffu, m, o));
    float s = expf(v0 - m) + ((lane < 8) ? expf(v1 - m) : 0.f);
    #pragma unroll
    for (int o = 16; o; o >>= 1) s += __shfl_xor_sync(0xffffffffu, s, o);
    float l = m + logf(s);
    row[lane] = v0 - l;
    if (lane < 8) row[32 + lane] = v1 - l;
}

// --------------------------------- launch -----------------------------------
extern "C" void kernel_launch(void* const* d_in, const int* in_sizes, int n_in,
                              void* d_out, int out_size)
{
    const float* x    = (const float*)d_in[0];
    const int*   ei   = (const int*)  d_in[1];
    const float* wmul = (const float*)d_in[2];
    const float* W1   = (const float*)d_in[3];
    const float* b1   = (const float*)d_in[4];
    const float* m1w0 = (const float*)d_in[5];
    const float* m1a  = (const float*)d_in[6];
    const float* m1w1 = (const float*)d_in[7];
    const float* m1b1 = (const float*)d_in[8];
    const float* W2   = (const float*)d_in[9];
    const float* b2   = (const float*)d_in[10];
    const float* m2w0 = (const float*)d_in[11];
    const float* m2a  = (const float*)d_in[12];
    const float* m2w1 = (const float*)d_in[13];
    const float* m2b1 = (const float*)d_in[14];
    float* out = (float*)d_out;

    const int* src = ei;            // edge_index[0]
    const int* dst = ei + N_EDGES;  // edge_index[1]

    float *p_h, *p_e, *p_sum, *p_out1, *p_h2;
    __half *p_w1h, *p_w0h, *p_xh, *p_W1t, *p_eh;
    cudaGetSymbolAddress((void**)&p_h,    g_h);
    cudaGetSymbolAddress((void**)&p_e,    g_e);
    cudaGetSymbolAddress((void**)&p_eh,   g_eh);
    cudaGetSymbolAddress((void**)&p_sum,  g_sum);
    cudaGetSymbolAddress((void**)&p_out1, g_out1);
    cudaGetSymbolAddress((void**)&p_h2,   g_h2);
    cudaGetSymbolAddress((void**)&p_w1h,  g_w1h);
    cudaGetSymbolAddress((void**)&p_w0h,  g_w0h);
    cudaGetSymbolAddress((void**)&p_xh,   g_xh);
    cudaGetSymbolAddress((void**)&p_W1t,  g_W1t);

    cudaFuncSetAttribute(edge_mlp_tc, cudaFuncAttributeMaxDynamicSharedMemorySize, TC_SMEM);

    // ---------------- conversions ----------------
    conv_x<<<(N_NODES * F_IN / 4 + 255) / 256, 256>>>(x, p_xh, N_NODES * F_IN / 4);
    conv_wt<F_IN, HID, F_IN><<<(HID * F_IN + 255) / 256, 256>>>(W1, p_W1t);
    conv_wt<HID,  HID, HID ><<<(HID * HID  + 255) / 256, 256>>>(m1w1, p_w1h);
    conv_wt<WDIM, HID, 64  ><<<(HID * 64   + 255) / 256, 256>>>(m1w0, p_w0h);

    // ---------------- layer 1 (C = 256) ----------------
    const int n1 = N_NODES * HID;
    zero_k<<<(n1 + 255) / 256, 256>>>(p_sum,  n1);
    zero_k<<<(n1 + 255) / 256, 256>>>(p_out1, n1);

    // h1 = x @ W1 + b1  (tensor cores)
    {
        dim3 grid((N_NODES + 127) / 128, HID / 64);
        node_gemm_tc<F_IN, HID><<<grid, 256>>>(p_xh, p_W1t, b1, p_h, N_NODES);
    }

    // e = exp(prelu(wmul@w0,a)@w1 + b1) fp16, segsum[src] += e
    {
        int grid = (N_EDGES + TC_TILES * TC_TE - 1) / (TC_TILES * TC_TE);
        edge_mlp_tc<<<grid, 256, TC_SMEM>>>(wmul, src, p_w0h, m1a, p_w1h, m1b1, p_eh, p_sum);
    }

    // hn = h1 / segsum (in place)
    div_k<<<(n1 + 255) / 256, 256>>>(p_h, p_sum, n1);

    // out1[dst] += e * hn[src]
    msg256<<<N_EDGES / 4, 256>>>(p_eh, src, dst, p_h, p_out1);

    // ---------------- layer 2 (C = 40) ----------------
    const int n2 = N_NODES * NCLS;
    zero_k<<<(n2 + 255) / 256, 256>>>(p_sum, n2);
    zero_k<<<(n2 + 255) / 256, 256>>>(out,   n2);

    // h2 = elu(out1) @ W2 + b2
    node_gemm<NCLS, HID, 10, 16, 2><<<(N_NODES + 31) / 32, 160>>>(p_out1, W2, b2, p_h2, N_NODES, 1);

    edge_mlp<NCLS, 10, 16, 4><<<N_EDGES / 64, 160>>>(wmul, src, m2w0, m2a, m2w1, m2b1, p_e, p_sum);

    // hn2 = h2 / segsum (in place)
    div_k<<<(n2 + 255) / 256, 256>>>(p_h2, p_sum, n2);

    msg40<<<N_EDGES / 32, 320>>>(p_e, src, dst, p_h2, out);

    logsoftmax40<<<(N_NODES + 7) / 8, 256>>>(out, N_NODES);
}

// round 6
// speedup vs baseline: 2.7153x; 1.2399x over previous
#include <cuda_runtime.h>
#include <cuda_fp16.h>
#include <stdint.h>
#include <math.h>

#define N_NODES 50000
#define N_EDGES 800000
#define F_IN    512
#define HID     256
#define NCLS    40
#define WDIM    50

// ------------------------- scratch (device globals) -------------------------
__device__ float  g_h   [(size_t)N_NODES * HID];    // h1 (then /= segsum)
__device__ float  g_e   [(size_t)N_EDGES * NCLS];   // layer-2 exp(ow) [E,40] f32
__device__ __half g_eh  [(size_t)N_EDGES * HID];    // layer-1 exp(ow) [E,256] fp16
__device__ float  g_sum [(size_t)N_NODES * HID];    // softmax denominators
__device__ float  g_out1[(size_t)N_NODES * HID];    // layer-1 aggregated output
__device__ float  g_h2  [(size_t)N_NODES * NCLS];   // h2 (then /= segsum)
__device__ __half g_w1h [(size_t)HID * HID];        // m1_w1^T fp16 [n][k]
__device__ __half g_w0h [(size_t)HID * 64];         // m1_w0^T fp16 [n][k pad 64]
__device__ __half g_xh  [(size_t)N_NODES * F_IN];   // x fp16
__device__ __half g_W1t [(size_t)HID * F_IN];       // W1^T fp16 [n][k]
__device__ __half g_w0h2[(size_t)64 * 64];          // m2_w0^T fp16 [n pad 64][k pad 64]
__device__ __half g_w1h2[(size_t)64 * 48];          // m2_w1^T fp16 [n pad 64][k pad 48]

// --------------------------- vector reductions ------------------------------
__device__ __forceinline__ void red_add_v4(float* p, float a, float b, float c, float d) {
    asm volatile("red.global.add.v4.f32 [%0], {%1,%2,%3,%4};"
                 :: "l"(p), "f"(a), "f"(b), "f"(c), "f"(d) : "memory");
}
__device__ __forceinline__ void red_add_v2(float* p, float a, float b) {
    asm volatile("red.global.add.v2.f32 [%0], {%1,%2};"
                 :: "l"(p), "f"(a), "f"(b) : "memory");
}

// ------------------------------- utilities ---------------------------------
__global__ void zero_k(float* __restrict__ p, int n) {
    int i = blockIdx.x * blockDim.x + threadIdx.x;
    if (i < n) p[i] = 0.0f;
}

__global__ void div_k(float* __restrict__ h, const float* __restrict__ s, int n) {
    int i = blockIdx.x * blockDim.x + threadIdx.x;
    if (i < n) h[i] = h[i] / s[i];
}

// x f32 -> fp16 (4-wide)
__global__ void conv_x(const float* __restrict__ x, __half* __restrict__ xh, int n4) {
    int i = blockIdx.x * blockDim.x + threadIdx.x;
    if (i < n4) {
        float4 v = *(const float4*)&x[i * 4];
        __half2* d = (__half2*)&xh[i * 4];
        d[0] = __floats2half2_rn(v.x, v.y);
        d[1] = __floats2half2_rn(v.z, v.w);
    }
}

// transpose+convert w [k][n] f32 -> wt fp16 [NP][KP], zero-pad k>=K, n>=N
template<int K, int N, int KP, int NP>
__global__ void conv_wt(const float* __restrict__ w, __half* __restrict__ wt) {
    int i = blockIdx.x * 256 + threadIdx.x;          // over NP*KP
    if (i >= NP * KP) return;
    int n = i / KP, k = i % KP;
    wt[i] = (k < K && n < N) ? __float2half(w[k * N + n]) : __half(0.0f);
}

// ------------------------------ mma helper ----------------------------------
__device__ __forceinline__ void mma16816(float c[4], const unsigned int a[4],
                                         unsigned int b0, unsigned int b1) {
    asm volatile(
        "mma.sync.aligned.m16n8k16.row.col.f32.f16.f16.f32 "
        "{%0,%1,%2,%3}, {%4,%5,%6,%7}, {%8,%9}, {%0,%1,%2,%3};\n"
        : "+f"(c[0]), "+f"(c[1]), "+f"(c[2]), "+f"(c[3])
        : "r"(a[0]), "r"(a[1]), "r"(a[2]), "r"(a[3]), "r"(b0), "r"(b1));
}

// ================= tensor-core node GEMM: out = A@B^T + bias =================
template<int K, int N>
__global__ void __launch_bounds__(256)
node_gemm_tc(const __half* __restrict__ A, const __half* __restrict__ Bt,
             const float* __restrict__ bias, float* __restrict__ out, int M)
{
    constexpr int BM = 128, BN = 64, BK = 64, KS = 72;
    __shared__ __half As[BM * KS];
    __shared__ __half Bs[BN * KS];

    const int tid = threadIdx.x;
    const int lane = tid & 31, warp = tid >> 5;
    const int g = lane >> 2, t2 = (lane & 3) * 2;
    const int wm = warp >> 2, wn = warp & 3;
    const int rBase = blockIdx.x * BM;
    const int cBase = blockIdx.y * BN;

    float c[4][2][4];
    #pragma unroll
    for (int mt = 0; mt < 4; mt++)
        #pragma unroll
        for (int nt = 0; nt < 2; nt++)
            { c[mt][nt][0]=0.f; c[mt][nt][1]=0.f; c[mt][nt][2]=0.f; c[mt][nt][3]=0.f; }

    for (int k0 = 0; k0 < K; k0 += BK) {
        #pragma unroll
        for (int i = 0; i < 4; i++) {
            int idx = tid + i * 256;
            int row = idx >> 3, seg = idx & 7;
            int gr = rBase + row;
            uint4 v = make_uint4(0u, 0u, 0u, 0u);
            if (gr < M) v = *(const uint4*)&A[(size_t)gr * K + k0 + seg * 8];
            *(uint4*)&As[row * KS + seg * 8] = v;
        }
        #pragma unroll
        for (int i = 0; i < 2; i++) {
            int idx = tid + i * 256;
            int n = idx >> 3, seg = idx & 7;
            *(uint4*)&Bs[n * KS + seg * 8] =
                *(const uint4*)&Bt[(size_t)(cBase + n) * K + k0 + seg * 8];
        }
        __syncthreads();

        #pragma unroll
        for (int ks = 0; ks < 4; ks++) {
            unsigned int a[4][4];
            #pragma unroll
            for (int mt = 0; mt < 4; mt++) {
                const __half* ap = &As[(wm * 64 + mt * 16 + g) * KS + ks * 16 + t2];
                a[mt][0] = *(const unsigned int*)ap;
                a[mt][1] = *(const unsigned int*)(ap + 8 * KS);
                a[mt][2] = *(const unsigned int*)(ap + 8);
                a[mt][3] = *(const unsigned int*)(ap + 8 * KS + 8);
            }
            #pragma unroll
            for (int nt = 0; nt < 2; nt++) {
                const __half* bp = &Bs[(wn * 16 + nt * 8 + g) * KS + ks * 16 + t2];
                unsigned int b0  = *(const unsigned int*)bp;
                unsigned int b1r = *(const unsigned int*)(bp + 8);
                #pragma unroll
                for (int mt = 0; mt < 4; mt++)
                    mma16816(c[mt][nt], a[mt], b0, b1r);
            }
        }
        __syncthreads();
    }

    #pragma unroll
    for (int mt = 0; mt < 4; mt++) {
        int r0 = rBase + wm * 64 + mt * 16 + g;
        #pragma unroll
        for (int nt = 0; nt < 2; nt++) {
            int col = cBase + wn * 16 + nt * 8 + t2;
            float2 bb = *(const float2*)&bias[col];
            if (r0 < M)
                *(float2*)&out[(size_t)r0 * N + col] =
                    make_float2(c[mt][nt][0] + bb.x, c[mt][nt][1] + bb.y);
            if (r0 + 8 < M)
                *(float2*)&out[(size_t)(r0 + 8) * N + col] =
                    make_float2(c[mt][nt][2] + bb.x, c[mt][nt][3] + bb.y);
        }
    }
}

// ========== layer-1 edge MLP: both stages on fp16 tensor cores ==============
#define TC_TILES   8
#define TC_TE      64
#define TC_BSTRIDE 264
#define TC_KP      64
#define TC_SMEM    ((HID*TC_BSTRIDE + HID*72 + TC_TE*TC_BSTRIDE + TC_TE*72) * 2)

__global__ void __launch_bounds__(256, 1)
edge_mlp_tc(const float* __restrict__ wmul, const int* __restrict__ src,
            const __half* __restrict__ w0h, const float* __restrict__ pa,
            const __half* __restrict__ w1h, const float* __restrict__ b1,
            __half* __restrict__ eout, float* __restrict__ segsum)
{
    extern __shared__ char smraw[];
    __half* sB   = (__half*)smraw;                    // [256][264] w1^T
    __half* sB0  = sB  + HID * TC_BSTRIDE;            // [256][72]  w0^T
    __half* tA   = sB0 + HID * 72;                    // [64][264]  t fp16
    __half* smwh = tA  + TC_TE * TC_BSTRIDE;          // [64][72]   wmul fp16

    const int tid  = threadIdx.x;
    const int lane = tid & 31, warp = tid >> 5;
    const int g = lane >> 2, t2 = (lane & 3) * 2;
    const int rowbase = (warp >> 2) * 32;
    const int colbase = (warp & 3) * 64;

    for (int idx = tid; idx < HID * (HID / 8); idx += 256) {
        int n = idx >> 5, kc = (idx & 31) * 8;
        *(uint4*)&sB[n * TC_BSTRIDE + kc] = *(const uint4*)&w1h[n * HID + kc];
    }
    for (int idx = tid; idx < HID * (TC_KP / 8); idx += 256) {
        int n = idx >> 3, kc = (idx & 7) * 8;
        *(uint4*)&sB0[n * 72 + kc] = *(const uint4*)&w0h[n * TC_KP + kc];
    }

    for (int tile = 0; tile < TC_TILES; tile++) {
        int eBase = blockIdx.x * (TC_TILES * TC_TE) + tile * TC_TE;
        if (eBase >= N_EDGES) break;

        for (int idx = tid; idx < TC_TE * 72; idx += 256) {
            int row = idx / 72, k = idx % 72;
            smwh[idx] = (k < WDIM)
                ? __float2half(wmul[(size_t)(eBase + row) * WDIM + k])
                : __half(0.0f);
        }
        __syncthreads();

        // ---- stage 1 (HMMA): t = prelu(wmul @ w0) -> tA fp16 ----
        {
            float c1[2][8][4];
            #pragma unroll
            for (int mt = 0; mt < 2; mt++)
                #pragma unroll
                for (int nt = 0; nt < 8; nt++)
                    { c1[mt][nt][0]=0.f; c1[mt][nt][1]=0.f; c1[mt][nt][2]=0.f; c1[mt][nt][3]=0.f; }

            #pragma unroll
            for (int ks = 0; ks < 4; ks++) {
                unsigned int a[2][4];
                #pragma unroll
                for (int mt = 0; mt < 2; mt++) {
                    const __half* ap = &smwh[(rowbase + mt * 16 + g) * 72 + ks * 16 + t2];
                    a[mt][0] = *(const unsigned int*)ap;
                    a[mt][1] = *(const unsigned int*)(ap + 8 * 72);
                    a[mt][2] = *(const unsigned int*)(ap + 8);
                    a[mt][3] = *(const unsigned int*)(ap + 8 * 72 + 8);
                }
                #pragma unroll
                for (int nt = 0; nt < 8; nt++) {
                    const __half* bp = &sB0[(colbase + nt * 8 + g) * 72 + ks * 16 + t2];
                    unsigned int b0  = *(const unsigned int*)bp;
                    unsigned int b1r = *(const unsigned int*)(bp + 8);
                    mma16816(c1[0][nt], a[0], b0, b1r);
                    mma16816(c1[1][nt], a[1], b0, b1r);
                }
            }

            #pragma unroll
            for (int mt = 0; mt < 2; mt++) {
                int r = rowbase + mt * 16 + g;
                #pragma unroll
                for (int nt = 0; nt < 8; nt++) {
                    int col = colbase + nt * 8 + t2;
                    float2 al = *(const float2*)&pa[col];
                    float v0 = c1[mt][nt][0] >= 0.f ? c1[mt][nt][0] : al.x * c1[mt][nt][0];
                    float v1 = c1[mt][nt][1] >= 0.f ? c1[mt][nt][1] : al.y * c1[mt][nt][1];
                    float v2 = c1[mt][nt][2] >= 0.f ? c1[mt][nt][2] : al.x * c1[mt][nt][2];
                    float v3 = c1[mt][nt][3] >= 0.f ? c1[mt][nt][3] : al.y * c1[mt][nt][3];
                    *(__half2*)&tA[r * TC_BSTRIDE + col]       = __floats2half2_rn(v0, v1);
                    *(__half2*)&tA[(r + 8) * TC_BSTRIDE + col] = __floats2half2_rn(v2, v3);
                }
            }
        }
        __syncthreads();

        // ---- stage 2 (HMMA): ow = t @ w1 ----
        float c[2][8][4];
        #pragma unroll
        for (int mt = 0; mt < 2; mt++)
            #pragma unroll
            for (int nt = 0; nt < 8; nt++)
                { c[mt][nt][0]=0.f; c[mt][nt][1]=0.f; c[mt][nt][2]=0.f; c[mt][nt][3]=0.f; }

        #pragma unroll
        for (int ks = 0; ks < 16; ks++) {
            unsigned int a[2][4];
            #pragma unroll
            for (int mt = 0; mt < 2; mt++) {
                const __half* ap = &tA[(rowbase + mt * 16 + g) * TC_BSTRIDE + ks * 16 + t2];
                a[mt][0] = *(const unsigned int*)ap;
                a[mt][1] = *(const unsigned int*)(ap + 8 * TC_BSTRIDE);
                a[mt][2] = *(const unsigned int*)(ap + 8);
                a[mt][3] = *(const unsigned int*)(ap + 8 * TC_BSTRIDE + 8);
            }
            #pragma unroll
            for (int nt = 0; nt < 8; nt++) {
                const __half* bp = &sB[(colbase + nt * 8 + g) * TC_BSTRIDE + ks * 16 + t2];
                unsigned int b0  = *(const unsigned int*)bp;
                unsigned int b1r = *(const unsigned int*)(bp + 8);
                mma16816(c[0][nt], a[0], b0, b1r);
                mma16816(c[1][nt], a[1], b0, b1r);
            }
        }

        // ---- epilogue: e = exp(ow + b1) -> fp16 store; segsum[src] += e ----
        #pragma unroll
        for (int mt = 0; mt < 2; mt++) {
            int r  = rowbase + mt * 16 + g;
            int e0 = eBase + r, e1 = e0 + 8;
            int s0 = src[e0],  s1 = src[e1];
            #pragma unroll
            for (int nt = 0; nt < 8; nt++) {
                int col = colbase + nt * 8 + t2;
                float2 bb = *(const float2*)&b1[col];
                float v0 = __expf(c[mt][nt][0] + bb.x);
                float v1 = __expf(c[mt][nt][1] + bb.y);
                float v2 = __expf(c[mt][nt][2] + bb.x);
                float v3 = __expf(c[mt][nt][3] + bb.y);
                *(__half2*)&eout[(size_t)e0 * HID + col] = __floats2half2_rn(v0, v1);
                *(__half2*)&eout[(size_t)e1 * HID + col] = __floats2half2_rn(v2, v3);
                red_add_v2(&segsum[(size_t)s0 * HID + col], v0, v1);
                red_add_v2(&segsum[(size_t)s1 * HID + col], v2, v3);
            }
        }
        __syncthreads();
    }
}

// ========== layer-2 edge MLP on tensor cores (N=40 pad 64, K2=40 pad 48) ====
#define T2_TILES 8
#define T2_TE    64

__global__ void __launch_bounds__(256, 1)
edge_mlp_tc2(const float* __restrict__ wmul, const int* __restrict__ src,
             const __half* __restrict__ w0h2, const float* __restrict__ pa,
             const __half* __restrict__ w1h2, const float* __restrict__ b1,
             float* __restrict__ eout, float* __restrict__ segsum)
{
    __shared__ __half sB0 [64 * 72];   // w0^T [64n][64k pad]
    __shared__ __half sB1 [64 * 56];   // w1^T [64n][48k pad]
    __shared__ __half tA  [64 * 56];   // t fp16 [64e][48k pad]
    __shared__ __half smwh[64 * 72];   // wmul fp16 [64e][64k pad]

    const int tid  = threadIdx.x;
    const int lane = tid & 31, warp = tid >> 5;
    const int g = lane >> 2, t2 = (lane & 3) * 2;
    const int rowbase = (warp >> 2) * 32;   // 0 / 32
    const int colbase = (warp & 3) * 16;    // 0/16/32/48

    // weights to smem once
    for (int idx = tid; idx < 64 * 8; idx += 256) {
        int n = idx >> 3, kc = (idx & 7) * 8;
        *(uint4*)&sB0[n * 72 + kc] = *(const uint4*)&w0h2[n * 64 + kc];
    }
    for (int idx = tid; idx < 64 * 6; idx += 256) {
        int n = idx / 6, kc = (idx % 6) * 8;
        *(uint4*)&sB1[n * 56 + kc] = *(const uint4*)&w1h2[n * 48 + kc];
    }

    for (int tile = 0; tile < T2_TILES; tile++) {
        int eBase = blockIdx.x * (T2_TILES * T2_TE) + tile * T2_TE;
        if (eBase >= N_EDGES) break;

        for (int idx = tid; idx < T2_TE * 72; idx += 256) {
            int row = idx / 72, k = idx % 72;
            smwh[idx] = (k < WDIM)
                ? __float2half(wmul[(size_t)(eBase + row) * WDIM + k])
                : __half(0.0f);
        }
        __syncthreads();

        // ---- stage 1 (HMMA): t = prelu(wmul @ w0) -> tA ----
        {
            float c1[2][2][4];
            #pragma unroll
            for (int mt = 0; mt < 2; mt++)
                #pragma unroll
                for (int nt = 0; nt < 2; nt++)
                    { c1[mt][nt][0]=0.f; c1[mt][nt][1]=0.f; c1[mt][nt][2]=0.f; c1[mt][nt][3]=0.f; }

            #pragma unroll
            for (int ks = 0; ks < 4; ks++) {
                unsigned int a[2][4];
                #pragma unroll
                for (int mt = 0; mt < 2; mt++) {
                    const __half* ap = &smwh[(rowbase + mt * 16 + g) * 72 + ks * 16 + t2];
                    a[mt][0] = *(const unsigned int*)ap;
                    a[mt][1] = *(const unsigned int*)(ap + 8 * 72);
                    a[mt][2] = *(const unsigned int*)(ap + 8);
                    a[mt][3] = *(const unsigned int*)(ap + 8 * 72 + 8);
                }
                #pragma unroll
                for (int nt = 0; nt < 2; nt++) {
                    const __half* bp = &sB0[(colbase + nt * 8 + g) * 72 + ks * 16 + t2];
                    unsigned int b0  = *(const unsigned int*)bp;
                    unsigned int b1r = *(const unsigned int*)(bp + 8);
                    mma16816(c1[0][nt], a[0], b0, b1r);
                    mma16816(c1[1][nt], a[1], b0, b1r);
                }
            }

            #pragma unroll
            for (int mt = 0; mt < 2; mt++) {
                int r = rowbase + mt * 16 + g;
                #pragma unroll
                for (int nt = 0; nt < 2; nt++) {
                    int col = colbase + nt * 8 + t2;
                    if (col < 48) {
                        float2 al = (col < NCLS) ? *(const float2*)&pa[col]
                                                 : make_float2(0.f, 0.f);
                        float v0 = c1[mt][nt][0] >= 0.f ? c1[mt][nt][0] : al.x * c1[mt][nt][0];
                        float v1 = c1[mt][nt][1] >= 0.f ? c1[mt][nt][1] : al.y * c1[mt][nt][1];
                        float v2 = c1[mt][nt][2] >= 0.f ? c1[mt][nt][2] : al.x * c1[mt][nt][2];
                        float v3 = c1[mt][nt][3] >= 0.f ? c1[mt][nt][3] : al.y * c1[mt][nt][3];
                        *(__half2*)&tA[r * 56 + col]       = __floats2half2_rn(v0, v1);
                        *(__half2*)&tA[(r + 8) * 56 + col] = __floats2half2_rn(v2, v3);
                    }
                }
            }
        }
        __syncthreads();

        // ---- stage 2 (HMMA): ow = t @ w1 ----
        float c[2][2][4];
        #pragma unroll
        for (int mt = 0; mt < 2; mt++)
            #pragma unroll
            for (int nt = 0; nt < 2; nt++)
                { c[mt][nt][0]=0.f; c[mt][nt][1]=0.f; c[mt][nt][2]=0.f; c[mt][nt][3]=0.f; }

        #pragma unroll
        for (int ks = 0; ks < 3; ks++) {
            unsigned int a[2][4];
            #pragma unroll
            for (int mt = 0; mt < 2; mt++) {
                const __half* ap = &tA[(rowbase + mt * 16 + g) * 56 + ks * 16 + t2];
                a[mt][0] = *(const unsigned int*)ap;
                a[mt][1] = *(const unsigned int*)(ap + 8 * 56);
                a[mt][2] = *(const unsigned int*)(ap + 8);
                a[mt][3] = *(const unsigned int*)(ap + 8 * 56 + 8);
            }
            #pragma unroll
            for (int nt = 0; nt < 2; nt++) {
                const __half* bp = &sB1[(colbase + nt * 8 + g) * 56 + ks * 16 + t2];
                unsigned int b0  = *(const unsigned int*)bp;
                unsigned int b1r = *(const unsigned int*)(bp + 8);
                mma16816(c[0][nt], a[0], b0, b1r);
                mma16816(c[1][nt], a[1], b0, b1r);
            }
        }

        // ---- epilogue: e = exp(ow + b1); store f32 [E,40]; segsum += e ----
        #pragma unroll
        for (int mt = 0; mt < 2; mt++) {
            int r  = rowbase + mt * 16 + g;
            int e0 = eBase + r, e1 = e0 + 8;
            int s0 = src[e0],  s1 = src[e1];
            #pragma unroll
            for (int nt = 0; nt < 2; nt++) {
                int col = colbase + nt * 8 + t2;
                if (col < NCLS) {
                    float2 bb = *(const float2*)&b1[col];
                    float v0 = __expf(c[mt][nt][0] + bb.x);
                    float v1 = __expf(c[mt][nt][1] + bb.y);
                    float v2 = __expf(c[mt][nt][2] + bb.x);
                    float v3 = __expf(c[mt][nt][3] + bb.y);
                    *(float2*)&eout[(size_t)e0 * NCLS + col] = make_float2(v0, v1);
                    *(float2*)&eout[(size_t)e1 * NCLS + col] = make_float2(v2, v3);
                    red_add_v2(&segsum[(size_t)s0 * NCLS + col], v0, v1);
                    red_add_v2(&segsum[(size_t)s1 * NCLS + col], v2, v3);
                }
            }
        }
        __syncthreads();
    }
}

// ---------- message + scatter: out[dst] += e * hn[src]  (hn = h/segsum) ----
__global__ void msg256(const __half* __restrict__ ewh, const int* __restrict__ src,
                       const int* __restrict__ dst, const float* __restrict__ hn,
                       float* __restrict__ out)
{
    int tid  = threadIdx.x;
    int eloc = tid >> 6;
    int c0   = (tid & 63) * 4;
    int edge = blockIdx.x * 4 + eloc;
    int s = src[edge], d = dst[edge];
    const __half2* ep = (const __half2*)&ewh[(size_t)edge * HID + c0];
    float2 e01 = __half22float2(ep[0]);
    float2 e23 = __half22float2(ep[1]);
    float4 hv = *(const float4*)&hn[(size_t)s * HID + c0];
    red_add_v4(&out[(size_t)d * HID + c0],
               e01.x * hv.x, e01.y * hv.y, e23.x * hv.z, e23.y * hv.w);
}

__global__ void msg40(const float* __restrict__ ew, const int* __restrict__ src,
                      const int* __restrict__ dst, const float* __restrict__ hn,
                      float* __restrict__ out)
{
    int tid  = threadIdx.x;          // 320 threads: 32 edges x 10 col-groups
    int eloc = tid / 10;
    int c0   = (tid % 10) * 4;
    int edge = blockIdx.x * 32 + eloc;
    int s = src[edge], d = dst[edge];
    float4 ev = *(const float4*)&ew[(size_t)edge * NCLS + c0];
    float4 hv = *(const float4*)&hn[(size_t)s    * NCLS + c0];
    red_add_v4(&out[(size_t)d * NCLS + c0],
               ev.x * hv.x, ev.y * hv.y, ev.z * hv.z, ev.w * hv.w);
}

// ------------ node GEMM fp32 (layer-2, ELU fused into staging) ---------------
template<int C, int K, int CT, int RT, int VE>
__global__ void node_gemm(const float* __restrict__ A, const float* __restrict__ W,
                          const float* __restrict__ bias, float* __restrict__ out,
                          int M, int act_in)
{
    constexpr int TE = RT * VE;
    constexpr int KS = K + 4;
    constexpr int NT = CT * RT;
    __shared__ float As[TE * KS];

    const int tid = threadIdx.x;
    const int ct = tid % CT, rt = tid / CT;
    const int c0 = ct * 4, r0 = rt * VE;
    const int rBase = blockIdx.x * TE;

    for (int idx = tid; idx < TE * (K / 4); idx += NT) {
        int row = idx / (K / 4);
        int kc  = (idx % (K / 4)) * 4;
        int gr  = rBase + row;
        float4 v = make_float4(0.f, 0.f, 0.f, 0.f);
        if (gr < M) v = *(const float4*)&A[(size_t)gr * K + kc];
        if (act_in) {
            v.x = v.x > 0.f ? v.x : expm1f(v.x);
            v.y = v.y > 0.f ? v.y : expm1f(v.y);
            v.z = v.z > 0.f ? v.z : expm1f(v.z);
            v.w = v.w > 0.f ? v.w : expm1f(v.w);
        }
        *(float4*)&As[row * KS + kc] = v;
    }
    __syncthreads();

    float acc[VE][4];
    #pragma unroll
    for (int i = 0; i < VE; i++) { acc[i][0]=0.f; acc[i][1]=0.f; acc[i][2]=0.f; acc[i][3]=0.f; }

    #pragma unroll 4
    for (int k = 0; k < K; k++) {
        float4 w = *(const float4*)&W[k * C + c0];
        #pragma unroll
        for (int i = 0; i < VE; i++) {
            float a = As[(r0 + i) * KS + k];
            acc[i][0] += a * w.x; acc[i][1] += a * w.y;
            acc[i][2] += a * w.z; acc[i][3] += a * w.w;
        }
    }

    float4 b = *(const float4*)&bias[c0];
    #pragma unroll
    for (int i = 0; i < VE; i++) {
        int gr = rBase + r0 + i;
        if (gr < M) {
            float4 o = make_float4(acc[i][0]+b.x, acc[i][1]+b.y, acc[i][2]+b.z, acc[i][3]+b.w);
            *(float4*)&out[(size_t)gr * C + c0] = o;
        }
    }
}

// --------------------------- in-place log_softmax ---------------------------
__global__ void logsoftmax40(float* __restrict__ out, int M)
{
    int warp = (blockIdx.x * blockDim.x + threadIdx.x) >> 5;
    int lane = threadIdx.x & 31;
    if (warp >= M) return;
    float* row = out + (size_t)warp * NCLS;
    float v0 = row[lane];
    float v1 = (lane < 8) ? row[32 + lane] : -INFINITY;
    float m = fmaxf(v0, v1);
    #pragma unroll
    for (int o = 16; o; o >>= 1) m = fmaxf(m, __shfl_xor_sync(0xffffffffu, m, o));
    float s = expf(v0 - m) + ((lane < 8) ? expf(v1 - m) : 0.f);
    #pragma unroll
    for (int o = 16; o; o >>= 1) s += __shfl_xor_sync(0xffffffffu, s, o);
    float l = m + logf(s);
    row[lane] = v0 - l;
    if (lane < 8) row[32 + lane] = v1 - l;
}

// --------------------------------- launch -----------------------------------
extern "C" void kernel_launch(void* const* d_in, const int* in_sizes, int n_in,
                              void* d_out, int out_size)
{
    const float* x    = (const float*)d_in[0];
    const int*   ei   = (const int*)  d_in[1];
    const float* wmul = (const float*)d_in[2];
    const float* W1   = (const float*)d_in[3];
    const float* b1   = (const float*)d_in[4];
    const float* m1w0 = (const float*)d_in[5];
    const float* m1a  = (const float*)d_in[6];
    const float* m1w1 = (const float*)d_in[7];
    const float* m1b1 = (const float*)d_in[8];
    const float* W2   = (const float*)d_in[9];
    const float* b2   = (const float*)d_in[10];
    const float* m2w0 = (const float*)d_in[11];
    const float* m2a  = (const float*)d_in[12];
    const float* m2w1 = (const float*)d_in[13];
    const float* m2b1 = (const float*)d_in[14];
    float* out = (float*)d_out;

    const int* src = ei;            // edge_index[0]
    const int* dst = ei + N_EDGES;  // edge_index[1]

    float *p_h, *p_e, *p_sum, *p_out1, *p_h2;
    __half *p_w1h, *p_w0h, *p_xh, *p_W1t, *p_eh, *p_w0h2, *p_w1h2;
    cudaGetSymbolAddress((void**)&p_h,    g_h);
    cudaGetSymbolAddress((void**)&p_e,    g_e);
    cudaGetSymbolAddress((void**)&p_eh,   g_eh);
    cudaGetSymbolAddress((void**)&p_sum,  g_sum);
    cudaGetSymbolAddress((void**)&p_out1, g_out1);
    cudaGetSymbolAddress((void**)&p_h2,   g_h2);
    cudaGetSymbolAddress((void**)&p_w1h,  g_w1h);
    cudaGetSymbolAddress((void**)&p_w0h,  g_w0h);
    cudaGetSymbolAddress((void**)&p_xh,   g_xh);
    cudaGetSymbolAddress((void**)&p_W1t,  g_W1t);
    cudaGetSymbolAddress((void**)&p_w0h2, g_w0h2);
    cudaGetSymbolAddress((void**)&p_w1h2, g_w1h2);

    cudaFuncSetAttribute(edge_mlp_tc, cudaFuncAttributeMaxDynamicSharedMemorySize, TC_SMEM);

    // ---------------- conversions ----------------
    conv_x<<<(N_NODES * F_IN / 4 + 255) / 256, 256>>>(x, p_xh, N_NODES * F_IN / 4);
    conv_wt<F_IN, HID,  F_IN, HID><<<(HID * F_IN + 255) / 256, 256>>>(W1, p_W1t);
    conv_wt<HID,  HID,  HID,  HID><<<(HID * HID  + 255) / 256, 256>>>(m1w1, p_w1h);
    conv_wt<WDIM, HID,  64,   HID><<<(HID * 64   + 255) / 256, 256>>>(m1w0, p_w0h);
    conv_wt<WDIM, NCLS, 64,   64 ><<<(64 * 64    + 255) / 256, 256>>>(m2w0, p_w0h2);
    conv_wt<NCLS, NCLS, 48,   64 ><<<(64 * 48    + 255) / 256, 256>>>(m2w1, p_w1h2);

    // ---------------- layer 1 (C = 256) ----------------
    const int n1 = N_NODES * HID;
    zero_k<<<(n1 + 255) / 256, 256>>>(p_sum,  n1);
    zero_k<<<(n1 + 255) / 256, 256>>>(p_out1, n1);

    // h1 = x @ W1 + b1  (tensor cores)
    {
        dim3 grid((N_NODES + 127) / 128, HID / 64);
        node_gemm_tc<F_IN, HID><<<grid, 256>>>(p_xh, p_W1t, b1, p_h, N_NODES);
    }

    // e = exp(prelu(wmul@w0,a)@w1 + b1) fp16, segsum[src] += e
    {
        int grid = (N_EDGES + TC_TILES * TC_TE - 1) / (TC_TILES * TC_TE);
        edge_mlp_tc<<<grid, 256, TC_SMEM>>>(wmul, src, p_w0h, m1a, p_w1h, m1b1, p_eh, p_sum);
    }

    // hn = h1 / segsum (in place)
    div_k<<<(n1 + 255) / 256, 256>>>(p_h, p_sum, n1);

    // out1[dst] += e * hn[src]
    msg256<<<N_EDGES / 4, 256>>>(p_eh, src, dst, p_h, p_out1);

    // ---------------- layer 2 (C = 40) ----------------
    const int n2 = N_NODES * NCLS;
    zero_k<<<(n2 + 255) / 256, 256>>>(p_sum, n2);
    zero_k<<<(n2 + 255) / 256, 256>>>(out,   n2);

    // h2 = elu(out1) @ W2 + b2
    node_gemm<NCLS, HID, 10, 16, 2><<<(N_NODES + 31) / 32, 160>>>(p_out1, W2, b2, p_h2, N_NODES, 1);

    // layer-2 edge MLP on tensor cores
    {
        int grid = (N_EDGES + T2_TILES * T2_TE - 1) / (T2_TILES * T2_TE);
        edge_mlp_tc2<<<grid, 256>>>(wmul, src, p_w0h2, m2a, p_w1h2, m2b1, p_e, p_sum);
    }

    // hn2 = h2 / segsum (in place)
    div_k<<<(n2 + 255) / 256, 256>>>(p_h2, p_sum, n2);

    msg40<<<N_EDGES / 32, 320>>>(p_e, src, dst, p_h2, out);

    logsoftmax40<<<(N_NODES + 7) / 8, 256>>>(out, N_NODES);
}

// round 9
// speedup vs baseline: 2.9124x; 1.0726x over previous
#include <cuda_runtime.h>
#include <cuda_fp16.h>
#include <stdint.h>
#include <math.h>

#define N_NODES 50000
#define N_EDGES 800000
#define F_IN    512
#define HID     256
#define NCLS    40
#define WDIM    50

// ------------------------- scratch (device globals) -------------------------
__device__ float  g_h   [(size_t)N_NODES * HID];    // h1 f32
__device__ __half g_hh  [(size_t)N_NODES * HID];    // h1/segsum fp16
__device__ float  g_e   [(size_t)N_EDGES * NCLS];   // layer-2 exp(ow) [E,40] f32
__device__ __half g_eh  [(size_t)N_EDGES * HID];    // layer-1 exp(ow) [E,256] fp16
__device__ float  g_sum [(size_t)N_NODES * HID];    // softmax denominators
__device__ float  g_out1[(size_t)N_NODES * HID];    // layer-1 aggregated output
__device__ __half g_o1h [(size_t)N_NODES * HID];    // elu(out1) fp16
__device__ float  g_h2  [(size_t)N_NODES * NCLS];   // h2 (then /= segsum)
__device__ __half g_w1h [(size_t)HID * HID];        // m1_w1^T fp16 [n][k]
__device__ __half g_w0h [(size_t)HID * 64];         // m1_w0^T fp16 [n][k pad 64]
__device__ __half g_xh  [(size_t)N_NODES * F_IN];   // x fp16
__device__ __half g_W1t [(size_t)HID * F_IN];       // W1^T fp16 [n][k]
__device__ __half g_W2t [(size_t)64 * HID];         // W2^T fp16 [n pad 64][k=256]
__device__ __half g_w0h2[(size_t)64 * 64];          // m2_w0^T fp16 [n pad 64][k pad 64]
__device__ __half g_w1h2[(size_t)64 * 48];          // m2_w1^T fp16 [n pad 64][k pad 48]

// --------------------------- vector reductions ------------------------------
__device__ __forceinline__ void red_add_v4(float* p, float a, float b, float c, float d) {
    asm volatile("red.global.add.v4.f32 [%0], {%1,%2,%3,%4};"
                 :: "l"(p), "f"(a), "f"(b), "f"(c), "f"(d) : "memory");
}
__device__ __forceinline__ void red_add_v2(float* p, float a, float b) {
    asm volatile("red.global.add.v2.f32 [%0], {%1,%2};"
                 :: "l"(p), "f"(a), "f"(b) : "memory");
}

// ------------------------------- utilities ---------------------------------
__global__ void zero_k(float* __restrict__ p, int n) {
    int i = blockIdx.x * blockDim.x + threadIdx.x;
    if (i < n) p[i] = 0.0f;
}

__global__ void div_k(float* __restrict__ h, const float* __restrict__ s, int n) {
    int i = blockIdx.x * blockDim.x + threadIdx.x;
    if (i < n) h[i] = h[i] / s[i];
}

// hn fp16 = h/s
__global__ void div_conv(const float* __restrict__ h, const float* __restrict__ s,
                         __half* __restrict__ hh, int n) {
    int i = blockIdx.x * blockDim.x + threadIdx.x;
    if (i < n) hh[i] = __float2half(h[i] / s[i]);
}

// elu(out1) -> fp16
__global__ void elu_conv(const float* __restrict__ a, __half* __restrict__ o, int n) {
    int i = blockIdx.x * blockDim.x + threadIdx.x;
    if (i < n) {
        float v = a[i];
        o[i] = __float2half(v > 0.f ? v : expm1f(v));
    }
}

// x f32 -> fp16 (4-wide)
__global__ void conv_x(const float* __restrict__ x, __half* __restrict__ xh, int n4) {
    int i = blockIdx.x * blockDim.x + threadIdx.x;
    if (i < n4) {
        float4 v = *(const float4*)&x[i * 4];
        __half2* d = (__half2*)&xh[i * 4];
        d[0] = __floats2half2_rn(v.x, v.y);
        d[1] = __floats2half2_rn(v.z, v.w);
    }
}

// transpose+convert w [k][n] f32 -> wt fp16 [NP][KP], zero-pad k>=K, n>=N
template<int K, int N, int KP, int NP>
__global__ void conv_wt(const float* __restrict__ w, __half* __restrict__ wt) {
    int i = blockIdx.x * 256 + threadIdx.x;          // over NP*KP
    if (i >= NP * KP) return;
    int n = i / KP, k = i % KP;
    wt[i] = (k < K && n < N) ? __float2half(w[k * N + n]) : __half(0.0f);
}

// ------------------------------ mma helper ----------------------------------
__device__ __forceinline__ void mma16816(float c[4], const unsigned int a[4],
                                         unsigned int b0, unsigned int b1) {
    asm volatile(
        "mma.sync.aligned.m16n8k16.row.col.f32.f16.f16.f32 "
        "{%0,%1,%2,%3}, {%4,%5,%6,%7}, {%8,%9}, {%0,%1,%2,%3};\n"
        : "+f"(c[0]), "+f"(c[1]), "+f"(c[2]), "+f"(c[3])
        : "r"(a[0]), "r"(a[1]), "r"(a[2]), "r"(a[3]), "r"(b0), "r"(b1));
}

// ====== tensor-core node GEMM: out[M][NSTORE] = A@B^T + bias (N padded) =====
template<int K, int N, int NSTORE>
__global__ void __launch_bounds__(256)
node_gemm_tc(const __half* __restrict__ A, const __half* __restrict__ Bt,
             const float* __restrict__ bias, float* __restrict__ out, int M)
{
    constexpr int BM = 128, BK = 64, KS = 72;
    __shared__ __half As[BM * KS];
    __shared__ __half Bs[64 * KS];

    const int tid = threadIdx.x;
    const int lane = tid & 31, warp = tid >> 5;
    const int g = lane >> 2, t2 = (lane & 3) * 2;
    const int wm = warp >> 2, wn = warp & 3;
    const int rBase = blockIdx.x * BM;
    const int cBase = blockIdx.y * 64;

    float c[4][2][4];
    #pragma unroll
    for (int mt = 0; mt < 4; mt++)
        #pragma unroll
        for (int nt = 0; nt < 2; nt++)
            { c[mt][nt][0]=0.f; c[mt][nt][1]=0.f; c[mt][nt][2]=0.f; c[mt][nt][3]=0.f; }

    for (int k0 = 0; k0 < K; k0 += BK) {
        #pragma unroll
        for (int i = 0; i < 4; i++) {
            int idx = tid + i * 256;
            int row = idx >> 3, seg = idx & 7;
            int gr = rBase + row;
            uint4 v = make_uint4(0u, 0u, 0u, 0u);
            if (gr < M) v = *(const uint4*)&A[(size_t)gr * K + k0 + seg * 8];
            *(uint4*)&As[row * KS + seg * 8] = v;
        }
        #pragma unroll
        for (int i = 0; i < 2; i++) {
            int idx = tid + i * 256;
            int n = idx >> 3, seg = idx & 7;
            *(uint4*)&Bs[n * KS + seg * 8] =
                *(const uint4*)&Bt[(size_t)(cBase + n) * K + k0 + seg * 8];
        }
        __syncthreads();

        #pragma unroll
        for (int ks = 0; ks < 4; ks++) {
            unsigned int a[4][4];
            #pragma unroll
            for (int mt = 0; mt < 4; mt++) {
                const __half* ap = &As[(wm * 64 + mt * 16 + g) * KS + ks * 16 + t2];
                a[mt][0] = *(const unsigned int*)ap;
                a[mt][1] = *(const unsigned int*)(ap + 8 * KS);
                a[mt][2] = *(const unsigned int*)(ap + 8);
                a[mt][3] = *(const unsigned int*)(ap + 8 * KS + 8);
            }
            #pragma unroll
            for (int nt = 0; nt < 2; nt++) {
                const __half* bp = &Bs[(wn * 16 + nt * 8 + g) * KS + ks * 16 + t2];
                unsigned int b0  = *(const unsigned int*)bp;
                unsigned int b1r = *(const unsigned int*)(bp + 8);
                #pragma unroll
                for (int mt = 0; mt < 4; mt++)
                    mma16816(c[mt][nt], a[mt], b0, b1r);
            }
        }
        __syncthreads();
    }

    #pragma unroll
    for (int mt = 0; mt < 4; mt++) {
        int r0 = rBase + wm * 64 + mt * 16 + g;
        #pragma unroll
        for (int nt = 0; nt < 2; nt++) {
            int col = cBase + wn * 16 + nt * 8 + t2;
            if (col < NSTORE) {
                float2 bb = *(const float2*)&bias[col];
                if (r0 < M)
                    *(float2*)&out[(size_t)r0 * NSTORE + col] =
                        make_float2(c[mt][nt][0] + bb.x, c[mt][nt][1] + bb.y);
                if (r0 + 8 < M)
                    *(float2*)&out[(size_t)(r0 + 8) * NSTORE + col] =
                        make_float2(c[mt][nt][2] + bb.x, c[mt][nt][3] + bb.y);
            }
        }
    }
}

// ========== layer-1 edge MLP: both stages HMMA, 512 threads / 16 warps ======
#define TC_TILES   8
#define TC_TE      64
#define TC_BSTRIDE 264
#define TC_KP      64
#define TC_NT      512
#define TC_SMEM    ((HID*TC_BSTRIDE + HID*72 + TC_TE*TC_BSTRIDE + TC_TE*72) * 2)

__global__ void __launch_bounds__(TC_NT, 1)
edge_mlp_tc(const float* __restrict__ wmul, const int* __restrict__ src,
            const __half* __restrict__ w0h, const float* __restrict__ pa,
            const __half* __restrict__ w1h, const float* __restrict__ b1,
            __half* __restrict__ eout, float* __restrict__ segsum)
{
    extern __shared__ char smraw[];
    __half* sB   = (__half*)smraw;                    // [256][264] w1^T
    __half* sB0  = sB  + HID * TC_BSTRIDE;            // [256][72]  w0^T
    __half* tA   = sB0 + HID * 72;                    // [64][264]  t fp16
    __half* smwh = tA  + TC_TE * TC_BSTRIDE;          // [64][72]   wmul fp16

    const int tid  = threadIdx.x;
    const int lane = tid & 31, warp = tid >> 5;       // 16 warps
    const int g = lane >> 2, t2 = (lane & 3) * 2;
    const int wm = warp >> 2;                         // m-group 0-3 (16 rows each)
    const int wn = warp & 3;                          // n-group 0-3 (64 cols each)
    const int rowbase = wm * 16;
    const int colbase = wn * 64;

    for (int idx = tid; idx < HID * (HID / 8); idx += TC_NT) {
        int n = idx >> 5, kc = (idx & 31) * 8;
        *(uint4*)&sB[n * TC_BSTRIDE + kc] = *(const uint4*)&w1h[n * HID + kc];
    }
    for (int idx = tid; idx < HID * (TC_KP / 8); idx += TC_NT) {
        int n = idx >> 3, kc = (idx & 7) * 8;
        *(uint4*)&sB0[n * 72 + kc] = *(const uint4*)&w0h[n * TC_KP + kc];
    }

    for (int tile = 0; tile < TC_TILES; tile++) {
        int eBase = blockIdx.x * (TC_TILES * TC_TE) + tile * TC_TE;
        if (eBase >= N_EDGES) break;

        for (int idx = tid; idx < TC_TE * 72; idx += TC_NT) {
            int row = idx / 72, k = idx % 72;
            smwh[idx] = (k < WDIM)
                ? __float2half(wmul[(size_t)(eBase + row) * WDIM + k])
                : __half(0.0f);
        }
        __syncthreads();

        // ---- stage 1 (HMMA): t = prelu(wmul @ w0) -> tA fp16 ----
        {
            float c1[8][4];
            #pragma unroll
            for (int nt = 0; nt < 8; nt++)
                { c1[nt][0]=0.f; c1[nt][1]=0.f; c1[nt][2]=0.f; c1[nt][3]=0.f; }

            #pragma unroll
            for (int ks = 0; ks < 4; ks++) {
                unsigned int a[4];
                const __half* ap = &smwh[(rowbase + g) * 72 + ks * 16 + t2];
                a[0] = *(const unsigned int*)ap;
                a[1] = *(const unsigned int*)(ap + 8 * 72);
                a[2] = *(const unsigned int*)(ap + 8);
                a[3] = *(const unsigned int*)(ap + 8 * 72 + 8);
                #pragma unroll
                for (int nt = 0; nt < 8; nt++) {
                    const __half* bp = &sB0[(colbase + nt * 8 + g) * 72 + ks * 16 + t2];
                    unsigned int b0  = *(const unsigned int*)bp;
                    unsigned int b1r = *(const unsigned int*)(bp + 8);
                    mma16816(c1[nt], a, b0, b1r);
                }
            }

            int r = rowbase + g;
            #pragma unroll
            for (int nt = 0; nt < 8; nt++) {
                int col = colbase + nt * 8 + t2;
                float2 al = *(const float2*)&pa[col];
                float v0 = c1[nt][0] >= 0.f ? c1[nt][0] : al.x * c1[nt][0];
                float v1 = c1[nt][1] >= 0.f ? c1[nt][1] : al.y * c1[nt][1];
                float v2 = c1[nt][2] >= 0.f ? c1[nt][2] : al.x * c1[nt][2];
                float v3 = c1[nt][3] >= 0.f ? c1[nt][3] : al.y * c1[nt][3];
                *(__half2*)&tA[r * TC_BSTRIDE + col]       = __floats2half2_rn(v0, v1);
                *(__half2*)&tA[(r + 8) * TC_BSTRIDE + col] = __floats2half2_rn(v2, v3);
            }
        }
        __syncthreads();

        // ---- stage 2 (HMMA): ow = t @ w1 ----
        float c[8][4];
        #pragma unroll
        for (int nt = 0; nt < 8; nt++)
            { c[nt][0]=0.f; c[nt][1]=0.f; c[nt][2]=0.f; c[nt][3]=0.f; }

        #pragma unroll
        for (int ks = 0; ks < 16; ks++) {
            unsigned int a[4];
            const __half* ap = &tA[(rowbase + g) * TC_BSTRIDE + ks * 16 + t2];
            a[0] = *(const unsigned int*)ap;
            a[1] = *(const unsigned int*)(ap + 8 * TC_BSTRIDE);
            a[2] = *(const unsigned int*)(ap + 8);
            a[3] = *(const unsigned int*)(ap + 8 * TC_BSTRIDE + 8);
            #pragma unroll
            for (int nt = 0; nt < 8; nt++) {
                const __half* bp = &sB[(colbase + nt * 8 + g) * TC_BSTRIDE + ks * 16 + t2];
                unsigned int b0  = *(const unsigned int*)bp;
                unsigned int b1r = *(const unsigned int*)(bp + 8);
                mma16816(c[nt], a, b0, b1r);
            }
        }

        // ---- epilogue: e = exp(ow + b1) -> fp16 store; segsum[src] += e ----
        {
            int r  = rowbase + g;
            int e0 = eBase + r, e1 = e0 + 8;
            int s0 = src[e0],  s1 = src[e1];
            #pragma unroll
            for (int nt = 0; nt < 8; nt++) {
                int col = colbase + nt * 8 + t2;
                float2 bb = *(const float2*)&b1[col];
                float v0 = __expf(c[nt][0] + bb.x);
                float v1 = __expf(c[nt][1] + bb.y);
                float v2 = __expf(c[nt][2] + bb.x);
                float v3 = __expf(c[nt][3] + bb.y);
                *(__half2*)&eout[(size_t)e0 * HID + col] = __floats2half2_rn(v0, v1);
                *(__half2*)&eout[(size_t)e1 * HID + col] = __floats2half2_rn(v2, v3);
                red_add_v2(&segsum[(size_t)s0 * HID + col], v0, v1);
                red_add_v2(&segsum[(size_t)s1 * HID + col], v2, v3);
            }
        }
        __syncthreads();
    }
}

// ========== layer-2 edge MLP on tensor cores (N=40 pad 64, K2=40 pad 48) ====
#define T2_TILES 8
#define T2_TE    64

__global__ void __launch_bounds__(256, 1)
edge_mlp_tc2(const float* __restrict__ wmul, const int* __restrict__ src,
             const __half* __restrict__ w0h2, const float* __restrict__ pa,
             const __half* __restrict__ w1h2, const float* __restrict__ b1,
             float* __restrict__ eout, float* __restrict__ segsum)
{
    __shared__ __half sB0 [64 * 72];
    __shared__ __half sB1 [64 * 56];
    __shared__ __half tA  [64 * 56];
    __shared__ __half smwh[64 * 72];

    const int tid  = threadIdx.x;
    const int lane = tid & 31, warp = tid >> 5;
    const int g = lane >> 2, t2 = (lane & 3) * 2;
    const int rowbase = (warp >> 2) * 32;   // 0 / 32
    const int colbase = (warp & 3) * 16;    // 0/16/32/48

    for (int idx = tid; idx < 64 * 8; idx += 256) {
        int n = idx >> 3, kc = (idx & 7) * 8;
        *(uint4*)&sB0[n * 72 + kc] = *(const uint4*)&w0h2[n * 64 + kc];
    }
    for (int idx = tid; idx < 64 * 6; idx += 256) {
        int n = idx / 6, kc = (idx % 6) * 8;
        *(uint4*)&sB1[n * 56 + kc] = *(const uint4*)&w1h2[n * 48 + kc];
    }

    for (int tile = 0; tile < T2_TILES; tile++) {
        int eBase = blockIdx.x * (T2_TILES * T2_TE) + tile * T2_TE;
        if (eBase >= N_EDGES) break;

        for (int idx = tid; idx < T2_TE * 72; idx += 256) {
            int row = idx / 72, k = idx % 72;
            smwh[idx] = (k < WDIM)
                ? __float2half(wmul[(size_t)(eBase + row) * WDIM + k])
                : __half(0.0f);
        }
        __syncthreads();

        // ---- stage 1 (HMMA): t = prelu(wmul @ w0) -> tA ----
        {
            float c1[2][2][4];
            #pragma unroll
            for (int mt = 0; mt < 2; mt++)
                #pragma unroll
                for (int nt = 0; nt < 2; nt++)
                    { c1[mt][nt][0]=0.f; c1[mt][nt][1]=0.f; c1[mt][nt][2]=0.f; c1[mt][nt][3]=0.f; }

            #pragma unroll
            for (int ks = 0; ks < 4; ks++) {
                unsigned int a[2][4];
                #pragma unroll
                for (int mt = 0; mt < 2; mt++) {
                    const __half* ap = &smwh[(rowbase + mt * 16 + g) * 72 + ks * 16 + t2];
                    a[mt][0] = *(const unsigned int*)ap;
                    a[mt][1] = *(const unsigned int*)(ap + 8 * 72);
                    a[mt][2] = *(const unsigned int*)(ap + 8);
                    a[mt][3] = *(const unsigned int*)(ap + 8 * 72 + 8);
                }
                #pragma unroll
                for (int nt = 0; nt < 2; nt++) {
                    const __half* bp = &sB0[(colbase + nt * 8 + g) * 72 + ks * 16 + t2];
                    unsigned int b0  = *(const unsigned int*)bp;
                    unsigned int b1r = *(const unsigned int*)(bp + 8);
                    mma16816(c1[0][nt], a[0], b0, b1r);
                    mma16816(c1[1][nt], a[1], b0, b1r);
                }
            }

            #pragma unroll
            for (int mt = 0; mt < 2; mt++) {
                int r = rowbase + mt * 16 + g;
                #pragma unroll
                for (int nt = 0; nt < 2; nt++) {
                    int col = colbase + nt * 8 + t2;
                    if (col < 48) {
                        float2 al = (col < NCLS) ? *(const float2*)&pa[col]
                                                 : make_float2(0.f, 0.f);
                        float v0 = c1[mt][nt][0] >= 0.f ? c1[mt][nt][0] : al.x * c1[mt][nt][0];
                        float v1 = c1[mt][nt][1] >= 0.f ? c1[mt][nt][1] : al.y * c1[mt][nt][1];
                        float v2 = c1[mt][nt][2] >= 0.f ? c1[mt][nt][2] : al.x * c1[mt][nt][2];
                        float v3 = c1[mt][nt][3] >= 0.f ? c1[mt][nt][3] : al.y * c1[mt][nt][3];
                        *(__half2*)&tA[r * 56 + col]       = __floats2half2_rn(v0, v1);
                        *(__half2*)&tA[(r + 8) * 56 + col] = __floats2half2_rn(v2, v3);
                    }
                }
            }
        }
        __syncthreads();

        // ---- stage 2 (HMMA): ow = t @ w1 ----
        float c[2][2][4];
        #pragma unroll
        for (int mt = 0; mt < 2; mt++)
            #pragma unroll
            for (int nt = 0; nt < 2; nt++)
                { c[mt][nt][0]=0.f; c[mt][nt][1]=0.f; c[mt][nt][2]=0.f; c[mt][nt][3]=0.f; }

        #pragma unroll
        for (int ks = 0; ks < 3; ks++) {
            unsigned int a[2][4];
            #pragma unroll
            for (int mt = 0; mt < 2; mt++) {
                const __half* ap = &tA[(rowbase + mt * 16 + g) * 56 + ks * 16 + t2];
                a[mt][0] = *(const unsigned int*)ap;
                a[mt][1] = *(const unsigned int*)(ap + 8 * 56);
                a[mt][2] = *(const unsigned int*)(ap + 8);
                a[mt][3] = *(const unsigned int*)(ap + 8 * 56 + 8);
            }
            #pragma unroll
            for (int nt = 0; nt < 2; nt++) {
                const __half* bp = &sB1[(colbase + nt * 8 + g) * 56 + ks * 16 + t2];
                unsigned int b0  = *(const unsigned int*)bp;
                unsigned int b1r = *(const unsigned int*)(bp + 8);
                mma16816(c[0][nt], a[0], b0, b1r);
                mma16816(c[1][nt], a[1], b0, b1r);
            }
        }

        // ---- epilogue ----
        #pragma unroll
        for (int mt = 0; mt < 2; mt++) {
            int r  = rowbase + mt * 16 + g;
            int e0 = eBase + r, e1 = e0 + 8;
            int s0 = src[e0],  s1 = src[e1];
            #pragma unroll
            for (int nt = 0; nt < 2; nt++) {
                int col = colbase + nt * 8 + t2;
                if (col < NCLS) {
                    float2 bb = *(const float2*)&b1[col];
                    float v0 = __expf(c[mt][nt][0] + bb.x);
                    float v1 = __expf(c[mt][nt][1] + bb.y);
                    float v2 = __expf(c[mt][nt][2] + bb.x);
                    float v3 = __expf(c[mt][nt][3] + bb.y);
                    *(float2*)&eout[(size_t)e0 * NCLS + col] = make_float2(v0, v1);
                    *(float2*)&eout[(size_t)e1 * NCLS + col] = make_float2(v2, v3);
                    red_add_v2(&segsum[(size_t)s0 * NCLS + col], v0, v1);
                    red_add_v2(&segsum[(size_t)s1 * NCLS + col], v2, v3);
                }
            }
        }
        __syncthreads();
    }
}

// ---------- message + scatter: out[dst] += e * hn[src]  (both fp16) --------
__global__ void msg256(const __half* __restrict__ ewh, const int* __restrict__ src,
                       const int* __restrict__ dst, const __half* __restrict__ hn,
                       float* __restrict__ out)
{
    int tid  = threadIdx.x;
    int eloc = tid >> 6;
    int c0   = (tid & 63) * 4;
    int edge = blockIdx.x * 4 + eloc;
    int s = src[edge], d = dst[edge];
    const __half2* ep = (const __half2*)&ewh[(size_t)edge * HID + c0];
    const __half2* hp = (const __half2*)&hn[(size_t)s * HID + c0];
    float2 e01 = __half22float2(ep[0]);
    float2 e23 = __half22float2(ep[1]);
    float2 h01 = __half22float2(hp[0]);
    float2 h23 = __half22float2(hp[1]);
    red_add_v4(&out[(size_t)d * HID + c0],
               e01.x * h01.x, e01.y * h01.y, e23.x * h23.x, e23.y * h23.y);
}

__global__ void msg40(const float* __restrict__ ew, const int* __restrict__ src,
                      const int* __restrict__ dst, const float* __restrict__ hn,
                      float* __restrict__ out)
{
    int tid  = threadIdx.x;          // 320 threads: 32 edges x 10 col-groups
    int eloc = tid / 10;
    int c0   = (tid % 10) * 4;
    int edge = blockIdx.x * 32 + eloc;
    int s = src[edge], d = dst[edge];
    float4 ev = *(const float4*)&ew[(size_t)edge * NCLS + c0];
    float4 hv = *(const float4*)&hn[(size_t)s    * NCLS + c0];
    red_add_v4(&out[(size_t)d * NCLS + c0],
               ev.x * hv.x, ev.y * hv.y, ev.z * hv.z, ev.w * hv.w);
}

// --------------------------- in-place log_softmax ---------------------------
__global__ void logsoftmax40(float* __restrict__ out, int M)
{
    int warp = (blockIdx.x * blockDim.x + threadIdx.x) >> 5;
    int lane = threadIdx.x & 31;
    if (warp >= M) return;
    float* row = out + (size_t)warp * NCLS;
    float v0 = row[lane];
    float v1 = (lane < 8) ? row[32 + lane] : -INFINITY;
    float m = fmaxf(v0, v1);
    #pragma unroll
    for (int o = 16; o; o >>= 1) m = fmaxf(m, __shfl_xor_sync(0xffffffffu, m, o));
    float s = expf(v0 - m) + ((lane < 8) ? expf(v1 - m) : 0.f);
    #pragma unroll
    for (int o = 16; o; o >>= 1) s += __shfl_xor_sync(0xffffffffu, s, o);
    float l = m + logf(s);
    row[lane] = v0 - l;
    if (lane < 8) row[32 + lane] = v1 - l;
}

// --------------------------------- launch -----------------------------------
extern "C" void kernel_launch(void* const* d_in, const int* in_sizes, int n_in,
                              void* d_out, int out_size)
{
    const float* x    = (const float*)d_in[0];
    const int*   ei   = (const int*)  d_in[1];
    const float* wmul = (const float*)d_in[2];
    const float* W1   = (const float*)d_in[3];
    const float* b1   = (const float*)d_in[4];
    const float* m1w0 = (const float*)d_in[5];
    const float* m1a  = (const float*)d_in[6];
    const float* m1w1 = (const float*)d_in[7];
    const float* m1b1 = (const float*)d_in[8];
    const float* W2   = (const float*)d_in[9];
    const float* b2   = (const float*)d_in[10];
    const float* m2w0 = (const float*)d_in[11];
    const float* m2a  = (const float*)d_in[12];
    const float* m2w1 = (const float*)d_in[13];
    const float* m2b1 = (const float*)d_in[14];
    float* out = (float*)d_out;

    const int* src = ei;            // edge_index[0]
    const int* dst = ei + N_EDGES;  // edge_index[1]

    float *p_h, *p_e, *p_sum, *p_out1, *p_h2;
    __half *p_w1h, *p_w0h, *p_xh, *p_W1t, *p_W2t, *p_eh, *p_w0h2, *p_w1h2, *p_hh, *p_o1h;
    cudaGetSymbolAddress((void**)&p_h,    g_h);
    cudaGetSymbolAddress((void**)&p_hh,   g_hh);
    cudaGetSymbolAddress((void**)&p_e,    g_e);
    cudaGetSymbolAddress((void**)&p_eh,   g_eh);
    cudaGetSymbolAddress((void**)&p_sum,  g_sum);
    cudaGetSymbolAddress((void**)&p_out1, g_out1);
    cudaGetSymbolAddress((void**)&p_o1h,  g_o1h);
    cudaGetSymbolAddress((void**)&p_h2,   g_h2);
    cudaGetSymbolAddress((void**)&p_w1h,  g_w1h);
    cudaGetSymbolAddress((void**)&p_w0h,  g_w0h);
    cudaGetSymbolAddress((void**)&p_xh,   g_xh);
    cudaGetSymbolAddress((void**)&p_W1t,  g_W1t);
    cudaGetSymbolAddress((void**)&p_W2t,  g_W2t);
    cudaGetSymbolAddress((void**)&p_w0h2, g_w0h2);
    cudaGetSymbolAddress((void**)&p_w1h2, g_w1h2);

    cudaFuncSetAttribute(edge_mlp_tc, cudaFuncAttributeMaxDynamicSharedMemorySize, TC_SMEM);

    const int n1 = N_NODES * HID;
    const int n2 = N_NODES * NCLS;

    // launches 1-3: minimal prerequisites for edge_mlp_tc (capture lands on #4)
    conv_wt<HID,  HID,  HID,  HID><<<(HID * HID + 255) / 256, 256>>>(m1w1, p_w1h);  // 1
    conv_wt<WDIM, HID,  64,   HID><<<(HID * 64  + 255) / 256, 256>>>(m1w0, p_w0h);  // 2
    zero_k<<<(n1 + 255) / 256, 256>>>(p_sum, n1);                                   // 3

    // 4: THE kernel — e = exp(prelu(wmul@w0,a)@w1 + b1) fp16, segsum[src] += e
    {
        int grid = (N_EDGES + TC_TILES * TC_TE - 1) / (TC_TILES * TC_TE);
        edge_mlp_tc<<<grid, TC_NT, TC_SMEM>>>(wmul, src, p_w0h, m1a, p_w1h, m1b1, p_eh, p_sum);
    }

    // remaining conversions + h1 GEMM
    conv_x<<<(N_NODES * F_IN / 4 + 255) / 256, 256>>>(x, p_xh, N_NODES * F_IN / 4);
    conv_wt<F_IN, HID,  F_IN, HID><<<(HID * F_IN + 255) / 256, 256>>>(W1, p_W1t);
    conv_wt<HID,  NCLS, HID,  64 ><<<(64 * HID   + 255) / 256, 256>>>(W2, p_W2t);
    conv_wt<WDIM, NCLS, 64,   64 ><<<(64 * 64    + 255) / 256, 256>>>(m2w0, p_w0h2);
    conv_wt<NCLS, NCLS, 48,   64 ><<<(64 * 48    + 255) / 256, 256>>>(m2w1, p_w1h2);
    zero_k<<<(n1 + 255) / 256, 256>>>(p_out1, n1);

    // h1 = x @ W1 + b1  (tensor cores)
    {
        dim3 grid((N_NODES + 127) / 128, HID / 64);
        node_gemm_tc<F_IN, HID, HID><<<grid, 256>>>(p_xh, p_W1t, b1, p_h, N_NODES);
    }

    // hn = fp16(h1 / segsum)
    div_conv<<<(n1 + 255) / 256, 256>>>(p_h, p_sum, p_hh, n1);

    // out1[dst] += e * hn[src]
    msg256<<<N_EDGES / 4, 256>>>(p_eh, src, dst, p_hh, p_out1);

    // ---------------- layer 2 (C = 40) ----------------
    zero_k<<<(n2 + 255) / 256, 256>>>(p_sum, n2);
    zero_k<<<(n2 + 255) / 256, 256>>>(out,   n2);

    // h2 = elu(out1) @ W2 + b2  (tensor cores, N padded to 64)
    elu_conv<<<(n1 + 255) / 256, 256>>>(p_out1, p_o1h, n1);
    {
        dim3 grid((N_NODES + 127) / 128, 1);
        node_gemm_tc<HID, 64, NCLS><<<grid, 256>>>(p_o1h, p_W2t, b2, p_h2, N_NODES);
    }

    // layer-2 edge MLP on tensor cores
    {
        int grid = (N_EDGES + T2_TILES * T2_TE - 1) / (T2_TILES * T2_TE);
        edge_mlp_tc2<<<grid, 256>>>(wmul, src, p_w0h2, m2a, p_w1h2, m2b1, p_e, p_sum);
    }

    // hn2 = h2 / segsum (in place)
    div_k<<<(n2 + 255) / 256, 256>>>(p_h2, p_sum, n2);

    msg40<<<N_EDGES / 32, 320>>>(p_e, src, dst, p_h2, out);

    logsoftmax40<<<(N_NODES + 7) / 8, 256>>>(out, N_NODES);
}

// round 10
// speedup vs baseline: 2.9202x; 1.0027x over previous
#include <cuda_runtime.h>
#include <cuda_fp16.h>
#include <stdint.h>
#include <math.h>

#define N_NODES 50000
#define N_EDGES 800000
#define F_IN    512
#define HID     256
#define NCLS    40
#define WDIM    50

// ------------------------- scratch (device globals) -------------------------
__device__ float  g_h   [(size_t)N_NODES * HID];    // h1 f32
__device__ __half g_hh  [(size_t)N_NODES * HID];    // h1/segsum fp16
__device__ float  g_e   [(size_t)N_EDGES * NCLS];   // layer-2 exp(ow) [E,40] f32
__device__ __half g_eh  [(size_t)N_EDGES * HID];    // layer-1 exp(ow) [E,256] fp16
__device__ float  g_sum [(size_t)N_NODES * HID];    // softmax denominators
__device__ float  g_out1[(size_t)N_NODES * HID];    // layer-1 aggregated output
__device__ __half g_o1h [(size_t)N_NODES * HID];    // elu(out1) fp16
__device__ float  g_h2  [(size_t)N_NODES * NCLS];   // h2 (then /= segsum)
__device__ __half g_w1h [(size_t)HID * HID];        // m1_w1^T fp16 [n][k]
__device__ __half g_w0h [(size_t)HID * 64];         // m1_w0^T fp16 [n][k pad 64]
__device__ __half g_xh  [(size_t)N_NODES * F_IN];   // x fp16
__device__ __half g_W1t [(size_t)HID * F_IN];       // W1^T fp16 [n][k]
__device__ __half g_W2t [(size_t)64 * HID];         // W2^T fp16 [n pad 64][k=256]
__device__ __half g_w0h2[(size_t)64 * 64];          // m2_w0^T fp16 [n pad 64][k pad 64]
__device__ __half g_w1h2[(size_t)64 * 48];          // m2_w1^T fp16 [n pad 64][k pad 48]

// --------------------------- vector reductions ------------------------------
__device__ __forceinline__ void red_add_v4(float* p, float a, float b, float c, float d) {
    asm volatile("red.global.add.v4.f32 [%0], {%1,%2,%3,%4};"
                 :: "l"(p), "f"(a), "f"(b), "f"(c), "f"(d) : "memory");
}
__device__ __forceinline__ void red_add_v2(float* p, float a, float b) {
    asm volatile("red.global.add.v2.f32 [%0], {%1,%2};"
                 :: "l"(p), "f"(a), "f"(b) : "memory");
}

// ------------------------------- utilities ---------------------------------
__global__ void zero_k(float* __restrict__ p, int n) {
    int i = blockIdx.x * blockDim.x + threadIdx.x;
    if (i < n) p[i] = 0.0f;
}

__global__ void div_k(float* __restrict__ h, const float* __restrict__ s, int n) {
    int i = blockIdx.x * blockDim.x + threadIdx.x;
    if (i < n) h[i] = h[i] / s[i];
}

__global__ void div_conv(const float* __restrict__ h, const float* __restrict__ s,
                         __half* __restrict__ hh, int n) {
    int i = blockIdx.x * blockDim.x + threadIdx.x;
    if (i < n) hh[i] = __float2half(h[i] / s[i]);
}

__global__ void elu_conv(const float* __restrict__ a, __half* __restrict__ o, int n) {
    int i = blockIdx.x * blockDim.x + threadIdx.x;
    if (i < n) {
        float v = a[i];
        o[i] = __float2half(v > 0.f ? v : expm1f(v));
    }
}

__global__ void conv_x(const float* __restrict__ x, __half* __restrict__ xh, int n4) {
    int i = blockIdx.x * blockDim.x + threadIdx.x;
    if (i < n4) {
        float4 v = *(const float4*)&x[i * 4];
        __half2* d = (__half2*)&xh[i * 4];
        d[0] = __floats2half2_rn(v.x, v.y);
        d[1] = __floats2half2_rn(v.z, v.w);
    }
}

template<int K, int N, int KP, int NP>
__global__ void conv_wt(const float* __restrict__ w, __half* __restrict__ wt) {
    int i = blockIdx.x * 256 + threadIdx.x;
    if (i >= NP * KP) return;
    int n = i / KP, k = i % KP;
    wt[i] = (k < K && n < N) ? __float2half(w[k * N + n]) : __half(0.0f);
}

// ------------------------------ mma helpers ---------------------------------
__device__ __forceinline__ void mma16816(float c[4], const unsigned int a[4],
                                         unsigned int b0, unsigned int b1) {
    asm volatile(
        "mma.sync.aligned.m16n8k16.row.col.f32.f16.f16.f32 "
        "{%0,%1,%2,%3}, {%4,%5,%6,%7}, {%8,%9}, {%0,%1,%2,%3};\n"
        : "+f"(c[0]), "+f"(c[1]), "+f"(c[2]), "+f"(c[3])
        : "r"(a[0]), "r"(a[1]), "r"(a[2]), "r"(a[3]), "r"(b0), "r"(b1));
}

__device__ __forceinline__ unsigned int sm_addr(const void* p) {
    return (unsigned int)__cvta_generic_to_shared(p);
}
__device__ __forceinline__ void ldsm4(unsigned int r[4], unsigned int addr) {
    asm volatile("ldmatrix.sync.aligned.m8n8.x4.shared.b16 {%0,%1,%2,%3}, [%4];"
                 : "=r"(r[0]), "=r"(r[1]), "=r"(r[2]), "=r"(r[3]) : "r"(addr));
}

// ====== tensor-core node GEMM: out[M][NSTORE] = A@B^T + bias (N padded) =====
template<int K, int N, int NSTORE>
__global__ void __launch_bounds__(256)
node_gemm_tc(const __half* __restrict__ A, const __half* __restrict__ Bt,
             const float* __restrict__ bias, float* __restrict__ out, int M)
{
    constexpr int BM = 128, BK = 64, KS = 72;
    __shared__ __half As[BM * KS];
    __shared__ __half Bs[64 * KS];

    const int tid = threadIdx.x;
    const int lane = tid & 31, warp = tid >> 5;
    const int g = lane >> 2, t2 = (lane & 3) * 2;
    const int wm = warp >> 2, wn = warp & 3;
    const int rBase = blockIdx.x * BM;
    const int cBase = blockIdx.y * 64;

    // LDSM base addresses (fixed smem layout)
    unsigned int aB[4], bB;
    #pragma unroll
    for (int mt = 0; mt < 4; mt++)
        aB[mt] = sm_addr(&As[(wm * 64 + mt * 16 + (lane & 15)) * KS + ((lane >> 4) << 3)]);
    bB = sm_addr(&Bs[(wn * 16 + ((lane >> 4) << 3) + (lane & 7)) * KS + (((lane >> 3) & 1) << 3)]);

    float c[4][2][4];
    #pragma unroll
    for (int mt = 0; mt < 4; mt++)
        #pragma unroll
        for (int nt = 0; nt < 2; nt++)
            { c[mt][nt][0]=0.f; c[mt][nt][1]=0.f; c[mt][nt][2]=0.f; c[mt][nt][3]=0.f; }

    for (int k0 = 0; k0 < K; k0 += BK) {
        #pragma unroll
        for (int i = 0; i < 4; i++) {
            int idx = tid + i * 256;
            int row = idx >> 3, seg = idx & 7;
            int gr = rBase + row;
            uint4 v = make_uint4(0u, 0u, 0u, 0u);
            if (gr < M) v = *(const uint4*)&A[(size_t)gr * K + k0 + seg * 8];
            *(uint4*)&As[row * KS + seg * 8] = v;
        }
        #pragma unroll
        for (int i = 0; i < 2; i++) {
            int idx = tid + i * 256;
            int n = idx >> 3, seg = idx & 7;
            *(uint4*)&Bs[n * KS + seg * 8] =
                *(const uint4*)&Bt[(size_t)(cBase + n) * K + k0 + seg * 8];
        }
        __syncthreads();

        #pragma unroll
        for (int ks = 0; ks < 4; ks++) {
            unsigned int b[4];
            ldsm4(b, bB + ks * 32);
            #pragma unroll
            for (int mt = 0; mt < 4; mt++) {
                unsigned int a[4];
                ldsm4(a, aB[mt] + ks * 32);
                mma16816(c[mt][0], a, b[0], b[1]);
                mma16816(c[mt][1], a, b[2], b[3]);
            }
        }
        __syncthreads();
    }

    #pragma unroll
    for (int mt = 0; mt < 4; mt++) {
        int r0 = rBase + wm * 64 + mt * 16 + g;
        #pragma unroll
        for (int nt = 0; nt < 2; nt++) {
            int col = cBase + wn * 16 + nt * 8 + t2;
            if (col < NSTORE) {
                float2 bb = *(const float2*)&bias[col];
                if (r0 < M)
                    *(float2*)&out[(size_t)r0 * NSTORE + col] =
                        make_float2(c[mt][nt][0] + bb.x, c[mt][nt][1] + bb.y);
                if (r0 + 8 < M)
                    *(float2*)&out[(size_t)(r0 + 8) * NSTORE + col] =
                        make_float2(c[mt][nt][2] + bb.x, c[mt][nt][3] + bb.y);
            }
        }
    }
}

// ========== layer-1 edge MLP: both stages HMMA (LDSM operands) ==============
#define TC_TILES   8
#define TC_TE      64
#define TC_BSTRIDE 264
#define TC_KP      64
#define TC_NT      512
#define TC_SMEM    ((HID*TC_BSTRIDE + HID*72 + TC_TE*TC_BSTRIDE + TC_TE*72) * 2)

__global__ void __launch_bounds__(TC_NT, 1)
edge_mlp_tc(const float* __restrict__ wmul, const int* __restrict__ src,
            const __half* __restrict__ w0h, const float* __restrict__ pa,
            const __half* __restrict__ w1h, const float* __restrict__ b1,
            __half* __restrict__ eout, float* __restrict__ segsum)
{
    extern __shared__ char smraw[];
    __half* sB   = (__half*)smraw;                    // [256][264] w1^T
    __half* sB0  = sB  + HID * TC_BSTRIDE;            // [256][72]  w0^T
    __half* tA   = sB0 + HID * 72;                    // [64][264]  t fp16
    __half* smwh = tA  + TC_TE * TC_BSTRIDE;          // [64][72]   wmul fp16

    const int tid  = threadIdx.x;
    const int lane = tid & 31, warp = tid >> 5;       // 16 warps
    const int g = lane >> 2, t2 = (lane & 3) * 2;
    const int rowbase = (warp >> 2) * 16;             // 4 m-groups x 16 rows
    const int colbase = (warp & 3) * 64;              // 4 n-groups x 64 cols

    // LDSM bases (fixed layout)
    const int lr = lane & 15, lh = (lane >> 4) << 3;       // A: row off, k-half
    const int br = ((lane >> 4) << 3) + (lane & 7);        // B: row-in-pair
    const int bh = ((lane >> 3) & 1) << 3;                 // B: k-half
    unsigned int aS1 = sm_addr(&smwh[(rowbase + lr) * 72 + lh]);
    unsigned int bS1 = sm_addr(&sB0 [(colbase + br) * 72 + bh]);
    unsigned int aS2 = sm_addr(&tA  [(rowbase + lr) * TC_BSTRIDE + lh]);
    unsigned int bS2 = sm_addr(&sB  [(colbase + br) * TC_BSTRIDE + bh]);

    for (int idx = tid; idx < HID * (HID / 8); idx += TC_NT) {
        int n = idx >> 5, kc = (idx & 31) * 8;
        *(uint4*)&sB[n * TC_BSTRIDE + kc] = *(const uint4*)&w1h[n * HID + kc];
    }
    for (int idx = tid; idx < HID * (TC_KP / 8); idx += TC_NT) {
        int n = idx >> 3, kc = (idx & 7) * 8;
        *(uint4*)&sB0[n * 72 + kc] = *(const uint4*)&w0h[n * TC_KP + kc];
    }

    for (int tile = 0; tile < TC_TILES; tile++) {
        int eBase = blockIdx.x * (TC_TILES * TC_TE) + tile * TC_TE;
        if (eBase >= N_EDGES) break;

        for (int idx = tid; idx < TC_TE * 72; idx += TC_NT) {
            int row = idx / 72, k = idx % 72;
            smwh[idx] = (k < WDIM)
                ? __float2half(wmul[(size_t)(eBase + row) * WDIM + k])
                : __half(0.0f);
        }
        __syncthreads();

        // ---- stage 1 (HMMA): t = prelu(wmul @ w0) -> tA fp16 ----
        {
            float c1[8][4];
            #pragma unroll
            for (int nt = 0; nt < 8; nt++)
                { c1[nt][0]=0.f; c1[nt][1]=0.f; c1[nt][2]=0.f; c1[nt][3]=0.f; }

            #pragma unroll
            for (int ks = 0; ks < 4; ks++) {
                unsigned int a[4];
                ldsm4(a, aS1 + ks * 32);
                #pragma unroll
                for (int pr = 0; pr < 4; pr++) {
                    unsigned int b[4];
                    ldsm4(b, bS1 + pr * (16 * 72 * 2) + ks * 32);
                    mma16816(c1[pr * 2],     a, b[0], b[1]);
                    mma16816(c1[pr * 2 + 1], a, b[2], b[3]);
                }
            }

            int r = rowbase + g;
            #pragma unroll
            for (int nt = 0; nt < 8; nt++) {
                int col = colbase + nt * 8 + t2;
                float2 al = *(const float2*)&pa[col];
                float v0 = c1[nt][0] >= 0.f ? c1[nt][0] : al.x * c1[nt][0];
                float v1 = c1[nt][1] >= 0.f ? c1[nt][1] : al.y * c1[nt][1];
                float v2 = c1[nt][2] >= 0.f ? c1[nt][2] : al.x * c1[nt][2];
                float v3 = c1[nt][3] >= 0.f ? c1[nt][3] : al.y * c1[nt][3];
                *(__half2*)&tA[r * TC_BSTRIDE + col]       = __floats2half2_rn(v0, v1);
                *(__half2*)&tA[(r + 8) * TC_BSTRIDE + col] = __floats2half2_rn(v2, v3);
            }
        }
        __syncthreads();

        // ---- stage 2 (HMMA): ow = t @ w1 ----
        float c[8][4];
        #pragma unroll
        for (int nt = 0; nt < 8; nt++)
            { c[nt][0]=0.f; c[nt][1]=0.f; c[nt][2]=0.f; c[nt][3]=0.f; }

        #pragma unroll
        for (int ks = 0; ks < 16; ks++) {
            unsigned int a[4];
            ldsm4(a, aS2 + ks * 32);
            #pragma unroll
            for (int pr = 0; pr < 4; pr++) {
                unsigned int b[4];
                ldsm4(b, bS2 + pr * (16 * TC_BSTRIDE * 2) + ks * 32);
                mma16816(c[pr * 2],     a, b[0], b[1]);
                mma16816(c[pr * 2 + 1], a, b[2], b[3]);
            }
        }

        // ---- epilogue: e = exp(ow + b1) -> fp16 store; segsum[src] += e ----
        {
            int r  = rowbase + g;
            int e0 = eBase + r, e1 = e0 + 8;
            int s0 = src[e0],  s1 = src[e1];
            #pragma unroll
            for (int nt = 0; nt < 8; nt++) {
                int col = colbase + nt * 8 + t2;
                float2 bb = *(const float2*)&b1[col];
                float v0 = __expf(c[nt][0] + bb.x);
                float v1 = __expf(c[nt][1] + bb.y);
                float v2 = __expf(c[nt][2] + bb.x);
                float v3 = __expf(c[nt][3] + bb.y);
                *(__half2*)&eout[(size_t)e0 * HID + col] = __floats2half2_rn(v0, v1);
                *(__half2*)&eout[(size_t)e1 * HID + col] = __floats2half2_rn(v2, v3);
                red_add_v2(&segsum[(size_t)s0 * HID + col], v0, v1);
                red_add_v2(&segsum[(size_t)s1 * HID + col], v2, v3);
            }
        }
        __syncthreads();
    }
}

// ========== layer-2 edge MLP on tensor cores (LDSM operands) ================
#define T2_TILES 8
#define T2_TE    64

__global__ void __launch_bounds__(256, 1)
edge_mlp_tc2(const float* __restrict__ wmul, const int* __restrict__ src,
             const __half* __restrict__ w0h2, const float* __restrict__ pa,
             const __half* __restrict__ w1h2, const float* __restrict__ b1,
             float* __restrict__ eout, float* __restrict__ segsum)
{
    __shared__ __half sB0 [64 * 72];
    __shared__ __half sB1 [64 * 56];
    __shared__ __half tA  [64 * 56];
    __shared__ __half smwh[64 * 72];

    const int tid  = threadIdx.x;
    const int lane = tid & 31, warp = tid >> 5;
    const int g = lane >> 2, t2 = (lane & 3) * 2;
    const int rowbase = (warp >> 2) * 32;   // 0 / 32
    const int colbase = (warp & 3) * 16;    // 0/16/32/48

    const int lr = lane & 15, lh = (lane >> 4) << 3;
    const int br = ((lane >> 4) << 3) + (lane & 7);
    const int bh = ((lane >> 3) & 1) << 3;
    unsigned int aS1[2], aS2[2];
    #pragma unroll
    for (int mt = 0; mt < 2; mt++) {
        aS1[mt] = sm_addr(&smwh[(rowbase + mt * 16 + lr) * 72 + lh]);
        aS2[mt] = sm_addr(&tA  [(rowbase + mt * 16 + lr) * 56 + lh]);
    }
    unsigned int bS1 = sm_addr(&sB0[(colbase + br) * 72 + bh]);
    unsigned int bS2 = sm_addr(&sB1[(colbase + br) * 56 + bh]);

    for (int idx = tid; idx < 64 * 8; idx += 256) {
        int n = idx >> 3, kc = (idx & 7) * 8;
        *(uint4*)&sB0[n * 72 + kc] = *(const uint4*)&w0h2[n * 64 + kc];
    }
    for (int idx = tid; idx < 64 * 6; idx += 256) {
        int n = idx / 6, kc = (idx % 6) * 8;
        *(uint4*)&sB1[n * 56 + kc] = *(const uint4*)&w1h2[n * 48 + kc];
    }

    for (int tile = 0; tile < T2_TILES; tile++) {
        int eBase = blockIdx.x * (T2_TILES * T2_TE) + tile * T2_TE;
        if (eBase >= N_EDGES) break;

        for (int idx = tid; idx < T2_TE * 72; idx += 256) {
            int row = idx / 72, k = idx % 72;
            smwh[idx] = (k < WDIM)
                ? __float2half(wmul[(size_t)(eBase + row) * WDIM + k])
                : __half(0.0f);
        }
        __syncthreads();

        // ---- stage 1 (HMMA): t = prelu(wmul @ w0) -> tA ----
        {
            float c1[2][2][4];
            #pragma unroll
            for (int mt = 0; mt < 2; mt++)
                #pragma unroll
                for (int nt = 0; nt < 2; nt++)
                    { c1[mt][nt][0]=0.f; c1[mt][nt][1]=0.f; c1[mt][nt][2]=0.f; c1[mt][nt][3]=0.f; }

            #pragma unroll
            for (int ks = 0; ks < 4; ks++) {
                unsigned int b[4];
                ldsm4(b, bS1 + ks * 32);
                #pragma unroll
                for (int mt = 0; mt < 2; mt++) {
                    unsigned int a[4];
                    ldsm4(a, aS1[mt] + ks * 32);
                    mma16816(c1[mt][0], a, b[0], b[1]);
                    mma16816(c1[mt][1], a, b[2], b[3]);
                }
            }

            #pragma unroll
            for (int mt = 0; mt < 2; mt++) {
                int r = rowbase + mt * 16 + g;
                #pragma unroll
                for (int nt = 0; nt < 2; nt++) {
                    int col = colbase + nt * 8 + t2;
                    if (col < 48) {
                        float2 al = (col < NCLS) ? *(const float2*)&pa[col]
                                                 : make_float2(0.f, 0.f);
                        float v0 = c1[mt][nt][0] >= 0.f ? c1[mt][nt][0] : al.x * c1[mt][nt][0];
                        float v1 = c1[mt][nt][1] >= 0.f ? c1[mt][nt][1] : al.y * c1[mt][nt][1];
                        float v2 = c1[mt][nt][2] >= 0.f ? c1[mt][nt][2] : al.x * c1[mt][nt][2];
                        float v3 = c1[mt][nt][3] >= 0.f ? c1[mt][nt][3] : al.y * c1[mt][nt][3];
                        *(__half2*)&tA[r * 56 + col]       = __floats2half2_rn(v0, v1);
                        *(__half2*)&tA[(r + 8) * 56 + col] = __floats2half2_rn(v2, v3);
                    }
                }
            }
        }
        __syncthreads();

        // ---- stage 2 (HMMA): ow = t @ w1 ----
        float c[2][2][4];
        #pragma unroll
        for (int mt = 0; mt < 2; mt++)
            #pragma unroll
            for (int nt = 0; nt < 2; nt++)
                { c[mt][nt][0]=0.f; c[mt][nt][1]=0.f; c[mt][nt][2]=0.f; c[mt][nt][3]=0.f; }

        #pragma unroll
        for (int ks = 0; ks < 3; ks++) {
            unsigned int b[4];
            ldsm4(b, bS2 + ks * 32);
            #pragma unroll
            for (int mt = 0; mt < 2; mt++) {
                unsigned int a[4];
                ldsm4(a, aS2[mt] + ks * 32);
                mma16816(c[mt][0], a, b[0], b[1]);
                mma16816(c[mt][1], a, b[2], b[3]);
            }
        }

        // ---- epilogue ----
        #pragma unroll
        for (int mt = 0; mt < 2; mt++) {
            int r  = rowbase + mt * 16 + g;
            int e0 = eBase + r, e1 = e0 + 8;
            int s0 = src[e0],  s1 = src[e1];
            #pragma unroll
            for (int nt = 0; nt < 2; nt++) {
                int col = colbase + nt * 8 + t2;
                if (col < NCLS) {
                    float2 bb = *(const float2*)&b1[col];
                    float v0 = __expf(c[mt][nt][0] + bb.x);
                    float v1 = __expf(c[mt][nt][1] + bb.y);
                    float v2 = __expf(c[mt][nt][2] + bb.x);
                    float v3 = __expf(c[mt][nt][3] + bb.y);
                    *(float2*)&eout[(size_t)e0 * NCLS + col] = make_float2(v0, v1);
                    *(float2*)&eout[(size_t)e1 * NCLS + col] = make_float2(v2, v3);
                    red_add_v2(&segsum[(size_t)s0 * NCLS + col], v0, v1);
                    red_add_v2(&segsum[(size_t)s1 * NCLS + col], v2, v3);
                }
            }
        }
        __syncthreads();
    }
}

// ---------- message + scatter: out[dst] += e * hn[src]  (both fp16) --------
__global__ void msg256(const __half* __restrict__ ewh, const int* __restrict__ src,
                       const int* __restrict__ dst, const __half* __restrict__ hn,
                       float* __restrict__ out)
{
    int tid  = threadIdx.x;
    int eloc = tid >> 6;
    int c0   = (tid & 63) * 4;
    int edge = blockIdx.x * 4 + eloc;
    int s = src[edge], d = dst[edge];
    const __half2* ep = (const __half2*)&ewh[(size_t)edge * HID + c0];
    const __half2* hp = (const __half2*)&hn[(size_t)s * HID + c0];
    float2 e01 = __half22float2(ep[0]);
    float2 e23 = __half22float2(ep[1]);
    float2 h01 = __half22float2(hp[0]);
    float2 h23 = __half22float2(hp[1]);
    red_add_v4(&out[(size_t)d * HID + c0],
               e01.x * h01.x, e01.y * h01.y, e23.x * h23.x, e23.y * h23.y);
}

__global__ void msg40(const float* __restrict__ ew, const int* __restrict__ src,
                      const int* __restrict__ dst, const float* __restrict__ hn,
                      float* __restrict__ out)
{
    int tid  = threadIdx.x;
    int eloc = tid / 10;
    int c0   = (tid % 10) * 4;
    int edge = blockIdx.x * 32 + eloc;
    int s = src[edge], d = dst[edge];
    float4 ev = *(const float4*)&ew[(size_t)edge * NCLS + c0];
    float4 hv = *(const float4*)&hn[(size_t)s    * NCLS + c0];
    red_add_v4(&out[(size_t)d * NCLS + c0],
               ev.x * hv.x, ev.y * hv.y, ev.z * hv.z, ev.w * hv.w);
}

// --------------------------- in-place log_softmax ---------------------------
__global__ void logsoftmax40(float* __restrict__ out, int M)
{
    int warp = (blockIdx.x * blockDim.x + threadIdx.x) >> 5;
    int lane = threadIdx.x & 31;
    if (warp >= M) return;
    float* row = out + (size_t)warp * NCLS;
    float v0 = row[lane];
    float v1 = (lane < 8) ? row[32 + lane] : -INFINITY;
    float m = fmaxf(v0, v1);
    #pragma unroll
    for (int o = 16; o; o >>= 1) m = fmaxf(m, __shfl_xor_sync(0xffffffffu, m, o));
    float s = expf(v0 - m) + ((lane < 8) ? expf(v1 - m) : 0.f);
    #pragma unroll
    for (int o = 16; o; o >>= 1) s += __shfl_xor_sync(0xffffffffu, s, o);
    float l = m + logf(s);
    row[lane] = v0 - l;
    if (lane < 8) row[32 + lane] = v1 - l;
}

// --------------------------------- launch -----------------------------------
extern "C" void kernel_launch(void* const* d_in, const int* in_sizes, int n_in,
                              void* d_out, int out_size)
{
    const float* x    = (const float*)d_in[0];
    const int*   ei   = (const int*)  d_in[1];
    const float* wmul = (const float*)d_in[2];
    const float* W1   = (const float*)d_in[3];
    const float* b1   = (const float*)d_in[4];
    const float* m1w0 = (const float*)d_in[5];
    const float* m1a  = (const float*)d_in[6];
    const float* m1w1 = (const float*)d_in[7];
    const float* m1b1 = (const float*)d_in[8];
    const float* W2   = (const float*)d_in[9];
    const float* b2   = (const float*)d_in[10];
    const float* m2w0 = (const float*)d_in[11];
    const float* m2a  = (const float*)d_in[12];
    const float* m2w1 = (const float*)d_in[13];
    const float* m2b1 = (const float*)d_in[14];
    float* out = (float*)d_out;

    const int* src = ei;            // edge_index[0]
    const int* dst = ei + N_EDGES;  // edge_index[1]

    float *p_h, *p_e, *p_sum, *p_out1, *p_h2;
    __half *p_w1h, *p_w0h, *p_xh, *p_W1t, *p_W2t, *p_eh, *p_w0h2, *p_w1h2, *p_hh, *p_o1h;
    cudaGetSymbolAddress((void**)&p_h,    g_h);
    cudaGetSymbolAddress((void**)&p_hh,   g_hh);
    cudaGetSymbolAddress((void**)&p_e,    g_e);
    cudaGetSymbolAddress((void**)&p_eh,   g_eh);
    cudaGetSymbolAddress((void**)&p_sum,  g_sum);
    cudaGetSymbolAddress((void**)&p_out1, g_out1);
    cudaGetSymbolAddress((void**)&p_o1h,  g_o1h);
    cudaGetSymbolAddress((void**)&p_h2,   g_h2);
    cudaGetSymbolAddress((void**)&p_w1h,  g_w1h);
    cudaGetSymbolAddress((void**)&p_w0h,  g_w0h);
    cudaGetSymbolAddress((void**)&p_xh,   g_xh);
    cudaGetSymbolAddress((void**)&p_W1t,  g_W1t);
    cudaGetSymbolAddress((void**)&p_W2t,  g_W2t);
    cudaGetSymbolAddress((void**)&p_w0h2, g_w0h2);
    cudaGetSymbolAddress((void**)&p_w1h2, g_w1h2);

    cudaFuncSetAttribute(edge_mlp_tc, cudaFuncAttributeMaxDynamicSharedMemorySize, TC_SMEM);

    const int n1 = N_NODES * HID;
    const int n2 = N_NODES * NCLS;

    // launches 1-3: minimal prerequisites for edge_mlp_tc (capture lands on #4)
    conv_wt<HID,  HID,  HID,  HID><<<(HID * HID + 255) / 256, 256>>>(m1w1, p_w1h);  // 1
    conv_wt<WDIM, HID,  64,   HID><<<(HID * 64  + 255) / 256, 256>>>(m1w0, p_w0h);  // 2
    zero_k<<<(n1 + 255) / 256, 256>>>(p_sum, n1);                                   // 3

    // 4: THE kernel — e = exp(prelu(wmul@w0,a)@w1 + b1) fp16, segsum[src] += e
    {
        int grid = (N_EDGES + TC_TILES * TC_TE - 1) / (TC_TILES * TC_TE);
        edge_mlp_tc<<<grid, TC_NT, TC_SMEM>>>(wmul, src, p_w0h, m1a, p_w1h, m1b1, p_eh, p_sum);
    }

    // remaining conversions + h1 GEMM
    conv_x<<<(N_NODES * F_IN / 4 + 255) / 256, 256>>>(x, p_xh, N_NODES * F_IN / 4);
    conv_wt<F_IN, HID,  F_IN, HID><<<(HID * F_IN + 255) / 256, 256>>>(W1, p_W1t);
    conv_wt<HID,  NCLS, HID,  64 ><<<(64 * HID   + 255) / 256, 256>>>(W2, p_W2t);
    conv_wt<WDIM, NCLS, 64,   64 ><<<(64 * 64    + 255) / 256, 256>>>(m2w0, p_w0h2);
    conv_wt<NCLS, NCLS, 48,   64 ><<<(64 * 48    + 255) / 256, 256>>>(m2w1, p_w1h2);
    zero_k<<<(n1 + 255) / 256, 256>>>(p_out1, n1);

    // h1 = x @ W1 + b1  (tensor cores)
    {
        dim3 grid((N_NODES + 127) / 128, HID / 64);
        node_gemm_tc<F_IN, HID, HID><<<grid, 256>>>(p_xh, p_W1t, b1, p_h, N_NODES);
    }

    // hn = fp16(h1 / segsum)
    div_conv<<<(n1 + 255) / 256, 256>>>(p_h, p_sum, p_hh, n1);

    // out1[dst] += e * hn[src]
    msg256<<<N_EDGES / 4, 256>>>(p_eh, src, dst, p_hh, p_out1);

    // ---------------- layer 2 (C = 40) ----------------
    zero_k<<<(n2 + 255) / 256, 256>>>(p_sum, n2);
    zero_k<<<(n2 + 255) / 256, 256>>>(out,   n2);

    // h2 = elu(out1) @ W2 + b2  (tensor cores, N padded to 64)
    elu_conv<<<(n1 + 255) / 256, 256>>>(p_out1, p_o1h, n1);
    {
        dim3 grid((N_NODES + 127) / 128, 1);
        node_gemm_tc<HID, 64, NCLS><<<grid, 256>>>(p_o1h, p_W2t, b2, p_h2, N_NODES);
    }

    // layer-2 edge MLP on tensor cores
    {
        int grid = (N_EDGES + T2_TILES * T2_TE - 1) / (T2_TILES * T2_TE);
        edge_mlp_tc2<<<grid, 256>>>(wmul, src, p_w0h2, m2a, p_w1h2, m2b1, p_e, p_sum);
    }

    // hn2 = h2 / segsum (in place)
    div_k<<<(n2 + 255) / 256, 256>>>(p_h2, p_sum, n2);

    msg40<<<N_EDGES / 32, 320>>>(p_e, src, dst, p_h2, out);

    logsoftmax40<<<(N_NODES + 7) / 8, 256>>>(out, N_NODES);
}

// round 13
// speedup vs baseline: 3.9886x; 1.3659x over previous
#include <cuda_runtime.h>
#include <cuda_fp16.h>
#include <stdint.h>
#include <math.h>

#define N_NODES 50000
#define N_EDGES 800000
#define F_IN    512
#define HID     256
#define NCLS    40
#define WDIM    50

// ------------------------- scratch (device globals) -------------------------
__device__ float  g_h   [(size_t)N_NODES * HID];    // h1 f32
__device__ __half g_hh  [(size_t)N_NODES * HID];    // h1/segsum fp16
__device__ float  g_e   [(size_t)N_EDGES * NCLS];   // layer-2 exp(ow) [E,40] f32
__device__ __half g_eh  [(size_t)N_EDGES * HID];    // layer-1 exp(ow) [E,256] fp16
__device__ float  g_sum [(size_t)N_NODES * HID];    // softmax denominators
__device__ float  g_out1[(size_t)N_NODES * HID];    // layer-1 aggregated output
__device__ __half g_o1h [(size_t)N_NODES * HID];    // elu(out1) fp16
__device__ float  g_h2  [(size_t)N_NODES * NCLS];   // h2 (then /= segsum)
__device__ __half g_w1h [(size_t)HID * HID];        // m1_w1^T fp16 [n][k]
__device__ __half g_w0h [(size_t)HID * 64];         // m1_w0^T fp16 [n][k pad 64]
__device__ __half g_xh  [(size_t)N_NODES * F_IN];   // x fp16
__device__ __half g_W1t [(size_t)HID * F_IN];       // W1^T fp16 [n][k]
__device__ __half g_W2t [(size_t)64 * HID];         // W2^T fp16 [n pad 64][k=256]
__device__ __half g_w0h2[(size_t)64 * 64];          // m2_w0^T fp16 [n pad 64][k pad 64]
__device__ __half g_w1h2[(size_t)64 * 48];          // m2_w1^T fp16 [n pad 64][k pad 48]

// --------------------------- vector reductions ------------------------------
__device__ __forceinline__ void red_add_v4(float* p, float a, float b, float c, float d) {
    asm volatile("red.global.add.v4.f32 [%0], {%1,%2,%3,%4};"
                 :: "l"(p), "f"(a), "f"(b), "f"(c), "f"(d) : "memory");
}
__device__ __forceinline__ void red_add_v2(float* p, float a, float b) {
    asm volatile("red.global.add.v2.f32 [%0], {%1,%2};"
                 :: "l"(p), "f"(a), "f"(b) : "memory");
}

// ------------------------------- utilities ---------------------------------
__global__ void zero_k(float* __restrict__ p, int n) {
    int i = blockIdx.x * blockDim.x + threadIdx.x;
    if (i < n) p[i] = 0.0f;
}

__global__ void div_k(float* __restrict__ h, const float* __restrict__ s, int n) {
    int i = blockIdx.x * blockDim.x + threadIdx.x;
    if (i < n) h[i] = h[i] / s[i];
}

__global__ void div_conv(const float* __restrict__ h, const float* __restrict__ s,
                         __half* __restrict__ hh, int n) {
    int i = blockIdx.x * blockDim.x + threadIdx.x;
    if (i < n) hh[i] = __float2half(h[i] / s[i]);
}

__global__ void elu_conv(const float* __restrict__ a, __half* __restrict__ o, int n) {
    int i = blockIdx.x * blockDim.x + threadIdx.x;
    if (i < n) {
        float v = a[i];
        o[i] = __float2half(v > 0.f ? v : expm1f(v));
    }
}

__global__ void conv_x(const float* __restrict__ x, __half* __restrict__ xh, int n4) {
    int i = blockIdx.x * blockDim.x + threadIdx.x;
    if (i < n4) {
        float4 v = *(const float4*)&x[i * 4];
        __half2* d = (__half2*)&xh[i * 4];
        d[0] = __floats2half2_rn(v.x, v.y);
        d[1] = __floats2half2_rn(v.z, v.w);
    }
}

template<int K, int N, int KP, int NP>
__global__ void conv_wt(const float* __restrict__ w, __half* __restrict__ wt) {
    int i = blockIdx.x * 256 + threadIdx.x;
    if (i >= NP * KP) return;
    int n = i / KP, k = i % KP;
    wt[i] = (k < K && n < N) ? __float2half(w[k * N + n]) : __half(0.0f);
}

// ------------------------------ mma helpers ---------------------------------
__device__ __forceinline__ void mma16816(float c[4], const unsigned int a[4],
                                         unsigned int b0, unsigned int b1) {
    asm volatile(
        "mma.sync.aligned.m16n8k16.row.col.f32.f16.f16.f32 "
        "{%0,%1,%2,%3}, {%4,%5,%6,%7}, {%8,%9}, {%0,%1,%2,%3};\n"
        : "+f"(c[0]), "+f"(c[1]), "+f"(c[2]), "+f"(c[3])
        : "r"(a[0]), "r"(a[1]), "r"(a[2]), "r"(a[3]), "r"(b0), "r"(b1));
}

__device__ __forceinline__ unsigned int sm_addr(const void* p) {
    return (unsigned int)__cvta_generic_to_shared(p);
}
__device__ __forceinline__ void ldsm4(unsigned int r[4], unsigned int addr) {
    asm volatile("ldmatrix.sync.aligned.m8n8.x4.shared.b16 {%0,%1,%2,%3}, [%4];"
                 : "=r"(r[0]), "=r"(r[1]), "=r"(r[2]), "=r"(r[3]) : "r"(addr));
}
// load float2 from global, convert to packed fp16x2
__device__ __forceinline__ unsigned int cvt2(const float* p) {
    float2 v = *(const float2*)p;
    __half2 h = __floats2half2_rn(v.x, v.y);
    return *reinterpret_cast<unsigned int*>(&h);
}
__device__ __forceinline__ unsigned int pack2(float a, float b) {
    __half2 h = __floats2half2_rn(a, b);
    return *reinterpret_cast<unsigned int*>(&h);
}
__device__ __forceinline__ float prelu1(float v, float a) {
    return v >= 0.f ? v : a * v;
}

// ====== tensor-core node GEMM: out[M][NSTORE] = A@B^T + bias (N padded) =====
template<int K, int N, int NSTORE>
__global__ void __launch_bounds__(256)
node_gemm_tc(const __half* __restrict__ A, const __half* __restrict__ Bt,
             const float* __restrict__ bias, float* __restrict__ out, int M)
{
    constexpr int BM = 128, BK = 64, KS = 72;
    __shared__ __half As[BM * KS];
    __shared__ __half Bs[64 * KS];

    const int tid = threadIdx.x;
    const int lane = tid & 31, warp = tid >> 5;
    const int g = lane >> 2, t2 = (lane & 3) * 2;
    const int wm = warp >> 2, wn = warp & 3;
    const int rBase = blockIdx.x * BM;
    const int cBase = blockIdx.y * 64;

    unsigned int aB[4], bB;
    #pragma unroll
    for (int mt = 0; mt < 4; mt++)
        aB[mt] = sm_addr(&As[(wm * 64 + mt * 16 + (lane & 15)) * KS + ((lane >> 4) << 3)]);
    bB = sm_addr(&Bs[(wn * 16 + ((lane >> 4) << 3) + (lane & 7)) * KS + (((lane >> 3) & 1) << 3)]);

    float c[4][2][4];
    #pragma unroll
    for (int mt = 0; mt < 4; mt++)
        #pragma unroll
        for (int nt = 0; nt < 2; nt++)
            { c[mt][nt][0]=0.f; c[mt][nt][1]=0.f; c[mt][nt][2]=0.f; c[mt][nt][3]=0.f; }

    for (int k0 = 0; k0 < K; k0 += BK) {
        #pragma unroll
        for (int i = 0; i < 4; i++) {
            int idx = tid + i * 256;
            int row = idx >> 3, seg = idx & 7;
            int gr = rBase + row;
            uint4 v = make_uint4(0u, 0u, 0u, 0u);
            if (gr < M) v = *(const uint4*)&A[(size_t)gr * K + k0 + seg * 8];
            *(uint4*)&As[row * KS + seg * 8] = v;
        }
        #pragma unroll
        for (int i = 0; i < 2; i++) {
            int idx = tid + i * 256;
            int n = idx >> 3, seg = idx & 7;
            *(uint4*)&Bs[n * KS + seg * 8] =
                *(const uint4*)&Bt[(size_t)(cBase + n) * K + k0 + seg * 8];
        }
        __syncthreads();

        #pragma unroll
        for (int ks = 0; ks < 4; ks++) {
            unsigned int b[4];
            ldsm4(b, bB + ks * 32);
            #pragma unroll
            for (int mt = 0; mt < 4; mt++) {
                unsigned int a[4];
                ldsm4(a, aB[mt] + ks * 32);
                mma16816(c[mt][0], a, b[0], b[1]);
                mma16816(c[mt][1], a, b[2], b[3]);
            }
        }
        __syncthreads();
    }

    #pragma unroll
    for (int mt = 0; mt < 4; mt++) {
        int r0 = rBase + wm * 64 + mt * 16 + g;
        #pragma unroll
        for (int nt = 0; nt < 2; nt++) {
            int col = cBase + wn * 16 + nt * 8 + t2;
            if (col < NSTORE) {
                float2 bb = *(const float2*)&bias[col];
                if (r0 < M)
                    *(float2*)&out[(size_t)r0 * NSTORE + col] =
                        make_float2(c[mt][nt][0] + bb.x, c[mt][nt][1] + bb.y);
                if (r0 + 8 < M)
                    *(float2*)&out[(size_t)(r0 + 8) * NSTORE + col] =
                        make_float2(c[mt][nt][2] + bb.x, c[mt][nt][3] + bb.y);
            }
        }
    }
}

// ========== layer-1 edge MLP: barrier-free, warp = 16 edges x 128 cols ======
// grid = (E1_BLK, 2): blockIdx.y picks the 128-col half of the 256 outputs.
// Stage-1 C fragments are prelu'd + packed in registers as stage-2 A fragments
// (identical thread mapping) — no tA smem, no __syncthreads in the main loop.
#define E1_BLK  400
#define E1_SMEM ((128*264 + 256*72) * 2)

__global__ void __launch_bounds__(512, 1)
edge_mlp_tc(const float* __restrict__ wmul, const int* __restrict__ src,
            const __half* __restrict__ w0h, const float* __restrict__ pa,
            const __half* __restrict__ w1h, const float* __restrict__ b1,
            __half* __restrict__ eout, float* __restrict__ segsum)
{
    extern __shared__ char smraw[];
    __half* sB  = (__half*)smraw;          // [128][264] w1^T rows colOff..+128
    __half* sB0 = sB + 128 * 264;          // [256][72]  w0^T (full)

    const int tid  = threadIdx.x;
    const int lane = tid & 31, warp = tid >> 5;   // 16 warps
    const int g = lane >> 2, t2 = (lane & 3) * 2;
    const int colOff = blockIdx.y * 128;

    for (int idx = tid; idx < 128 * 32; idx += 512) {
        int n = idx >> 5, kc = (idx & 31) * 8;
        *(uint4*)&sB[n * 264 + kc] = *(const uint4*)&w1h[(size_t)(colOff + n) * HID + kc];
    }
    for (int idx = tid; idx < 256 * 8; idx += 512) {
        int n = idx >> 3, kc = (idx & 7) * 8;
        *(uint4*)&sB0[n * 72 + kc] = *(const uint4*)&w0h[n * 64 + kc];
    }
    __syncthreads();

    const int br = ((lane >> 4) << 3) + (lane & 7);
    const int bh = ((lane >> 3) & 1) << 3;
    const unsigned int bS1 = sm_addr(&sB0[br * 72  + bh]);
    const unsigned int bS2 = sm_addr(&sB [br * 264 + bh]);

    for (int u = blockIdx.x * 16 + warp; u < N_EDGES / 16; u += E1_BLK * 16) {
        int e0 = u * 16;

        // ---- A fragments (wmul, fp32->fp16) straight from global ----
        const float* wr0 = wmul + (size_t)(e0 + g) * WDIM;
        const float* wr1 = wr0 + 8 * WDIM;
        unsigned int a[4][4];
        #pragma unroll
        for (int kb = 0; kb < 3; kb++) {
            a[kb][0] = cvt2(wr0 + kb * 16 + t2);
            a[kb][1] = cvt2(wr1 + kb * 16 + t2);
            a[kb][2] = cvt2(wr0 + kb * 16 + 8 + t2);
            a[kb][3] = cvt2(wr1 + kb * 16 + 8 + t2);
        }
        a[3][0] = (t2 == 0) ? cvt2(wr0 + 48) : 0u;
        a[3][1] = (t2 == 0) ? cvt2(wr1 + 48) : 0u;
        a[3][2] = 0u; a[3][3] = 0u;

        float c2[16][4];
        #pragma unroll
        for (int nt = 0; nt < 16; nt++)
            { c2[nt][0]=0.f; c2[nt][1]=0.f; c2[nt][2]=0.f; c2[nt][3]=0.f; }

        #pragma unroll
        for (int ks = 0; ks < 16; ks++) {
            // stage 1: t cols [16ks, 16ks+16) for our 16 edges
            float c1[2][4] = {{0.f,0.f,0.f,0.f},{0.f,0.f,0.f,0.f}};
            #pragma unroll
            for (int kb = 0; kb < 4; kb++) {
                unsigned int b[4];
                ldsm4(b, bS1 + ks * 2304 + kb * 32);   // 2304 = 16*72*2
                mma16816(c1[0], a[kb], b[0], b[1]);
                mma16816(c1[1], a[kb], b[2], b[3]);
            }
            // prelu + pack: C fragment == stage-2 A fragment layout
            float2 al0 = *(const float2*)&pa[ks * 16 + t2];
            float2 al1 = *(const float2*)&pa[ks * 16 + 8 + t2];
            unsigned int aa[4];
            aa[0] = pack2(prelu1(c1[0][0], al0.x), prelu1(c1[0][1], al0.y));
            aa[1] = pack2(prelu1(c1[0][2], al0.x), prelu1(c1[0][3], al0.y));
            aa[2] = pack2(prelu1(c1[1][0], al1.x), prelu1(c1[1][1], al1.y));
            aa[3] = pack2(prelu1(c1[1][2], al1.x), prelu1(c1[1][3], al1.y));
            // stage 2: accumulate into 128 output cols
            #pragma unroll
            for (int pr = 0; pr < 8; pr++) {
                unsigned int b[4];
                ldsm4(b, bS2 + pr * 8448 + ks * 32);   // 8448 = 16*264*2
                mma16816(c2[2 * pr],     aa, b[0], b[1]);
                mma16816(c2[2 * pr + 1], aa, b[2], b[3]);
            }
        }

        // ---- epilogue: e = exp(ow + b1) fp16; segsum[src] += e ----
        int ea = e0 + g, eb = ea + 8;
        int s0 = src[ea], s1 = src[eb];
        #pragma unroll
        for (int nt = 0; nt < 16; nt++) {
            int col = colOff + nt * 8 + t2;
            float2 bb = *(const float2*)&b1[col];
            float v0 = __expf(c2[nt][0] + bb.x);
            float v1 = __expf(c2[nt][1] + bb.y);
            float v2 = __expf(c2[nt][2] + bb.x);
            float v3 = __expf(c2[nt][3] + bb.y);
            *(__half2*)&eout[(size_t)ea * HID + col] = __floats2half2_rn(v0, v1);
            *(__half2*)&eout[(size_t)eb * HID + col] = __floats2half2_rn(v2, v3);
            red_add_v2(&segsum[(size_t)s0 * HID + col], v0, v1);
            red_add_v2(&segsum[(size_t)s1 * HID + col], v2, v3);
        }
    }
}

// ========== layer-2 edge MLP: barrier-free, warp = 16 edges x 40(64) cols ===
#define E2_BLK 400

__global__ void __launch_bounds__(512, 1)
edge_mlp_tc2(const float* __restrict__ wmul, const int* __restrict__ src,
             const __half* __restrict__ w0h2, const float* __restrict__ pa,
             const __half* __restrict__ w1h2, const float* __restrict__ b1,
             float* __restrict__ eout, float* __restrict__ segsum)
{
    __shared__ __half sB0[48 * 72];   // w0^T rows 0..47 (t cols, pad 48)
    __shared__ __half sB1[64 * 56];   // w1^T [64 out-cols][48 k]

    const int tid  = threadIdx.x;
    const int lane = tid & 31, warp = tid >> 5;
    const int g = lane >> 2, t2 = (lane & 3) * 2;

    for (int idx = tid; idx < 48 * 8; idx += 512) {
        int n = idx >> 3, kc = (idx & 7) * 8;
        *(uint4*)&sB0[n * 72 + kc] = *(const uint4*)&w0h2[n * 64 + kc];
    }
    for (int idx = tid; idx < 64 * 6; idx += 512) {
        int n = idx / 6, kc = (idx % 6) * 8;
        *(uint4*)&sB1[n * 56 + kc] = *(const uint4*)&w1h2[n * 48 + kc];
    }
    __syncthreads();

    const int br = ((lane >> 4) << 3) + (lane & 7);
    const int bh = ((lane >> 3) & 1) << 3;
    const unsigned int bS1 = sm_addr(&sB0[br * 72 + bh]);
    const unsigned int bS2 = sm_addr(&sB1[br * 56 + bh]);

    for (int u = blockIdx.x * 16 + warp; u < N_EDGES / 16; u += E2_BLK * 16) {
        int e0 = u * 16;

        const float* wr0 = wmul + (size_t)(e0 + g) * WDIM;
        const float* wr1 = wr0 + 8 * WDIM;
        unsigned int a[4][4];
        #pragma unroll
        for (int kb = 0; kb < 3; kb++) {
            a[kb][0] = cvt2(wr0 + kb * 16 + t2);
            a[kb][1] = cvt2(wr1 + kb * 16 + t2);
            a[kb][2] = cvt2(wr0 + kb * 16 + 8 + t2);
            a[kb][3] = cvt2(wr1 + kb * 16 + 8 + t2);
        }
        a[3][0] = (t2 == 0) ? cvt2(wr0 + 48) : 0u;
        a[3][1] = (t2 == 0) ? cvt2(wr1 + 48) : 0u;
        a[3][2] = 0u; a[3][3] = 0u;

        float c2[8][4];
        #pragma unroll
        for (int nt = 0; nt < 8; nt++)
            { c2[nt][0]=0.f; c2[nt][1]=0.f; c2[nt][2]=0.f; c2[nt][3]=0.f; }

        #pragma unroll
        for (int ks = 0; ks < 3; ks++) {
            float c1[2][4] = {{0.f,0.f,0.f,0.f},{0.f,0.f,0.f,0.f}};
            #pragma unroll
            for (int kb = 0; kb < 4; kb++) {
                unsigned int b[4];
                ldsm4(b, bS1 + ks * 2304 + kb * 32);
                mma16816(c1[0], a[kb], b[0], b[1]);
                mma16816(c1[1], a[kb], b[2], b[3]);
            }
            float2 al0 = *(const float2*)&pa[ks * 16 + t2];            // col <= 38
            float2 al1 = (ks < 2) ? *(const float2*)&pa[ks * 16 + 8 + t2]
                                  : make_float2(0.f, 0.f);             // pad cols: c1==0
            unsigned int aa[4];
            aa[0] = pack2(prelu1(c1[0][0], al0.x), prelu1(c1[0][1], al0.y));
            aa[1] = pack2(prelu1(c1[0][2], al0.x), prelu1(c1[0][3], al0.y));
            aa[2] = pack2(prelu1(c1[1][0], al1.x), prelu1(c1[1][1], al1.y));
            aa[3] = pack2(prelu1(c1[1][2], al1.x), prelu1(c1[1][3], al1.y));
            #pragma unroll
            for (int pr = 0; pr < 4; pr++) {
                unsigned int b[4];
                ldsm4(b, bS2 + pr * 1792 + ks * 32);   // 1792 = 16*56*2
                mma16816(c2[2 * pr],     aa, b[0], b[1]);
                mma16816(c2[2 * pr + 1], aa, b[2], b[3]);
            }
        }

        int ea = e0 + g, eb = ea + 8;
        int s0 = src[ea], s1 = src[eb];
        #pragma unroll
        for (int nt = 0; nt < 5; nt++) {              // cols 0..39 only
            int col = nt * 8 + t2;
            float2 bb = *(const float2*)&b1[col];
            float v0 = __expf(c2[nt][0] + bb.x);
            float v1 = __expf(c2[nt][1] + bb.y);
            float v2 = __expf(c2[nt][2] + bb.x);
            float v3 = __expf(c2[nt][3] + bb.y);
            *(float2*)&eout[(size_t)ea * NCLS + col] = make_float2(v0, v1);
            *(float2*)&eout[(size_t)eb * NCLS + col] = make_float2(v2, v3);
            red_add_v2(&segsum[(size_t)s0 * NCLS + col], v0, v1);
            red_add_v2(&segsum[(size_t)s1 * NCLS + col], v2, v3);
        }
    }
}

// ---------- message + scatter: out[dst] += e * hn[src]  (both fp16) --------
__global__ void msg256(const __half* __restrict__ ewh, const int* __restrict__ src,
                       const int* __restrict__ dst, const __half* __restrict__ hn,
                       float* __restrict__ out)
{
    int tid  = threadIdx.x;
    int eloc = tid >> 6;
    int c0   = (tid & 63) * 4;
    int edge = blockIdx.x * 4 + eloc;
    int s = src[edge], d = dst[edge];
    const __half2* ep = (const __half2*)&ewh[(size_t)edge * HID + c0];
    const __half2* hp = (const __half2*)&hn[(size_t)s * HID + c0];
    float2 e01 = __half22float2(ep[0]);
    float2 e23 = __half22float2(ep[1]);
    float2 h01 = __half22float2(hp[0]);
    float2 h23 = __half22float2(hp[1]);
    red_add_v4(&out[(size_t)d * HID + c0],
               e01.x * h01.x, e01.y * h01.y, e23.x * h23.x, e23.y * h23.y);
}

__global__ void msg40(const float* __restrict__ ew, const int* __restrict__ src,
                      const int* __restrict__ dst, const float* __restrict__ hn,
                      float* __restrict__ out)
{
    int tid  = threadIdx.x;
    int eloc = tid / 10;
    int c0   = (tid % 10) * 4;
    int edge = blockIdx.x * 32 + eloc;
    int s = src[edge], d = dst[edge];
    float4 ev = *(const float4*)&ew[(size_t)edge * NCLS + c0];
    float4 hv = *(const float4*)&hn[(size_t)s    * NCLS + c0];
    red_add_v4(&out[(size_t)d * NCLS + c0],
               ev.x * hv.x, ev.y * hv.y, ev.z * hv.z, ev.w * hv.w);
}

// --------------------------- in-place log_softmax ---------------------------
__global__ void logsoftmax40(float* __restrict__ out, int M)
{
    int warp = (blockIdx.x * blockDim.x + threadIdx.x) >> 5;
    int lane = threadIdx.x & 31;
    if (warp >= M) return;
    float* row = out + (size_t)warp * NCLS;
    float v0 = row[lane];
    float v1 = (lane < 8) ? row[32 + lane] : -INFINITY;
    float m = fmaxf(v0, v1);
    #pragma unroll
    for (int o = 16; o; o >>= 1) m = fmaxf(m, __shfl_xor_sync(0xffffffffu, m, o));
    float s = expf(v0 - m) + ((lane < 8) ? expf(v1 - m) : 0.f);
    #pragma unroll
    for (int o = 16; o; o >>= 1) s += __shfl_xor_sync(0xffffffffu, s, o);
    float l = m + logf(s);
    row[lane] = v0 - l;
    if (lane < 8) row[32 + lane] = v1 - l;
}

// --------------------------------- launch -----------------------------------
extern "C" void kernel_launch(void* const* d_in, const int* in_sizes, int n_in,
                              void* d_out, int out_size)
{
    const float* x    = (const float*)d_in[0];
    const int*   ei   = (const int*)  d_in[1];
    const float* wmul = (const float*)d_in[2];
    const float* W1   = (const float*)d_in[3];
    const float* b1   = (const float*)d_in[4];
    const float* m1w0 = (const float*)d_in[5];
    const float* m1a  = (const float*)d_in[6];
    const float* m1w1 = (const float*)d_in[7];
    const float* m1b1 = (const float*)d_in[8];
    const float* W2   = (const float*)d_in[9];
    const float* b2   = (const float*)d_in[10];
    const float* m2w0 = (const float*)d_in[11];
    const float* m2a  = (const float*)d_in[12];
    const float* m2w1 = (const float*)d_in[13];
    const float* m2b1 = (const float*)d_in[14];
    float* out = (float*)d_out;

    const int* src = ei;            // edge_index[0]
    const int* dst = ei + N_EDGES;  // edge_index[1]

    float *p_h, *p_e, *p_sum, *p_out1, *p_h2;
    __half *p_w1h, *p_w0h, *p_xh, *p_W1t, *p_W2t, *p_eh, *p_w0h2, *p_w1h2, *p_hh, *p_o1h;
    cudaGetSymbolAddress((void**)&p_h,    g_h);
    cudaGetSymbolAddress((void**)&p_hh,   g_hh);
    cudaGetSymbolAddress((void**)&p_e,    g_e);
    cudaGetSymbolAddress((void**)&p_eh,   g_eh);
    cudaGetSymbolAddress((void**)&p_sum,  g_sum);
    cudaGetSymbolAddress((void**)&p_out1, g_out1);
    cudaGetSymbolAddress((void**)&p_o1h,  g_o1h);
    cudaGetSymbolAddress((void**)&p_h2,   g_h2);
    cudaGetSymbolAddress((void**)&p_w1h,  g_w1h);
    cudaGetSymbolAddress((void**)&p_w0h,  g_w0h);
    cudaGetSymbolAddress((void**)&p_xh,   g_xh);
    cudaGetSymbolAddress((void**)&p_W1t,  g_W1t);
    cudaGetSymbolAddress((void**)&p_W2t,  g_W2t);
    cudaGetSymbolAddress((void**)&p_w0h2, g_w0h2);
    cudaGetSymbolAddress((void**)&p_w1h2, g_w1h2);

    cudaFuncSetAttribute(edge_mlp_tc, cudaFuncAttributeMaxDynamicSharedMemorySize, E1_SMEM);

    const int n1 = N_NODES * HID;
    const int n2 = N_NODES * NCLS;

    // launches 1-3: minimal prerequisites for edge_mlp_tc (capture lands on #4)
    conv_wt<HID,  HID,  HID,  HID><<<(HID * HID + 255) / 256, 256>>>(m1w1, p_w1h);  // 1
    conv_wt<WDIM, HID,  64,   HID><<<(HID * 64  + 255) / 256, 256>>>(m1w0, p_w0h);  // 2
    zero_k<<<(n1 + 255) / 256, 256>>>(p_sum, n1);                                   // 3

    // 4: THE kernel — e = exp(prelu(wmul@w0,a)@w1 + b1) fp16, segsum[src] += e
    {
        dim3 grid(E1_BLK, 2);
        edge_mlp_tc<<<grid, 512, E1_SMEM>>>(wmul, src, p_w0h, m1a, p_w1h, m1b1, p_eh, p_sum);
    }

    // remaining conversions + h1 GEMM
    conv_x<<<(N_NODES * F_IN / 4 + 255) / 256, 256>>>(x, p_xh, N_NODES * F_IN / 4);
    conv_wt<F_IN, HID,  F_IN, HID><<<(HID * F_IN + 255) / 256, 256>>>(W1, p_W1t);
    conv_wt<HID,  NCLS, HID,  64 ><<<(64 * HID   + 255) / 256, 256>>>(W2, p_W2t);
    conv_wt<WDIM, NCLS, 64,   64 ><<<(64 * 64    + 255) / 256, 256>>>(m2w0, p_w0h2);
    conv_wt<NCLS, NCLS, 48,   64 ><<<(64 * 48    + 255) / 256, 256>>>(m2w1, p_w1h2);
    zero_k<<<(n1 + 255) / 256, 256>>>(p_out1, n1);

    // h1 = x @ W1 + b1  (tensor cores)
    {
        dim3 grid((N_NODES + 127) / 128, HID / 64);
        node_gemm_tc<F_IN, HID, HID><<<grid, 256>>>(p_xh, p_W1t, b1, p_h, N_NODES);
    }

    // hn = fp16(h1 / segsum)
    div_conv<<<(n1 + 255) / 256, 256>>>(p_h, p_sum, p_hh, n1);

    // out1[dst] += e * hn[src]
    msg256<<<N_EDGES / 4, 256>>>(p_eh, src, dst, p_hh, p_out1);

    // ---------------- layer 2 (C = 40) ----------------
    zero_k<<<(n2 + 255) / 256, 256>>>(p_sum, n2);
    zero_k<<<(n2 + 255) / 256, 256>>>(out,   n2);

    // h2 = elu(out1) @ W2 + b2  (tensor cores, N padded to 64)
    elu_conv<<<(n1 + 255) / 256, 256>>>(p_out1, p_o1h, n1);
    {
        dim3 grid((N_NODES + 127) / 128, 1);
        node_gemm_tc<HID, 64, NCLS><<<grid, 256>>>(p_o1h, p_W2t, b2, p_h2, N_NODES);
    }

    // layer-2 edge MLP (barrier-free tensor cores)
    edge_mlp_tc2<<<E2_BLK, 512>>>(wmul, src, p_w0h2, m2a, p_w1h2, m2b1, p_e, p_sum);

    // hn2 = h2 / segsum (in place)
    div_k<<<(n2 + 255) / 256, 256>>>(p_h2, p_sum, n2);

    msg40<<<N_EDGES / 32, 320>>>(p_e, src, dst, p_h2, out);

    logsoftmax40<<<(N_NODES + 7) / 8, 256>>>(out, N_NODES);
}